// round 1
// baseline (speedup 1.0000x reference)
#include <cuda_runtime.h>
#include <cuda_bf16.h>
#include <math.h>

// ---------------- problem constants ----------------
#define BATCH 2
#define TSEQ 2048
#define BT (BATCH*TSEQ)          // 4096
#define DMODEL 2048
#define NHEADS 8
#define KVHEADS 4
#define GQA (NHEADS/KVHEADS)     // 2
#define HDIM 256
#define FFDIM 8192
#define WINDOW 1024
#define SOFTCAP 50.0f

// ---------------- scratch (no cudaMalloc allowed) ----------------
__device__ float g_h    [(size_t)BT*DMODEL];
__device__ float g_q    [(size_t)BT*NHEADS*HDIM];
__device__ float g_k    [(size_t)BT*KVHEADS*HDIM];
__device__ float g_v    [(size_t)BT*KVHEADS*HDIM];
__device__ float g_enc  [(size_t)BT*NHEADS*HDIM];
__device__ float g_aproj[(size_t)BT*DMODEL];
__device__ float g_ares [(size_t)BT*DMODEL];
__device__ float g_ffin [(size_t)BT*DMODEL];
__device__ float g_gates[(size_t)BT*2*FFDIM];
__device__ float g_act  [(size_t)BT*FFDIM];
__device__ float g_fout [(size_t)BT*DMODEL];

// ---------------- row-wise RMSNorm (D=2048), optional residual ----------------
// out = rmsnorm(in)*(1+scale) + (resid ? resid*skip : 0)
__global__ void rows_norm_kernel(const float* __restrict__ in,
                                 const float* __restrict__ scale,
                                 const float* __restrict__ resid,
                                 const float* __restrict__ skip,
                                 float* __restrict__ out)
{
    const int row = blockIdx.x;
    const int tid = threadIdx.x;
    const size_t base = (size_t)row * DMODEL;
    float vals[8];
    float ss = 0.f;
#pragma unroll
    for (int i = 0; i < 8; i++) {
        float v = in[base + tid + i*256];
        vals[i] = v; ss += v*v;
    }
    __shared__ float red[8];
#pragma unroll
    for (int o = 16; o; o >>= 1) ss += __shfl_xor_sync(0xffffffffu, ss, o);
    if ((tid & 31) == 0) red[tid >> 5] = ss;
    __syncthreads();
    if (tid < 32) {
        float t = (tid < 8) ? red[tid] : 0.f;
#pragma unroll
        for (int o = 4; o; o >>= 1) t += __shfl_xor_sync(0xffffffffu, t, o);
        if (tid == 0) red[0] = t;
    }
    __syncthreads();
    const float inv = rsqrtf(red[0] * (1.f/DMODEL) + 1e-6f);
    const float sk = skip ? skip[0] : 1.f;
#pragma unroll
    for (int i = 0; i < 8; i++) {
        const int d = tid + i*256;
        float o = vals[i] * inv * (1.f + (scale ? scale[d] : 0.f));
        if (resid) o += resid[base + d] * sk;
        out[base + d] = o;
    }
}

// ---------------- SGEMM 128x128x8, 256 threads, 8x8 microtile ----------------
// NN: B is [K,N] row-major (n contiguous).  grid.z batches weight/output heads.
__global__ __launch_bounds__(256, 2)
void sgemm_nn(const float* __restrict__ A, const float* __restrict__ B,
              float* __restrict__ C, int K, int lda, int ldb, int ldc,
              int wstride_z, int cstride_z)
{
    __shared__ float As[8][128];
    __shared__ float Bs[8][128];
    const float* Bz = B + (size_t)blockIdx.z * wstride_z;
    const int cbase = blockIdx.z * cstride_z;
    const int m0 = blockIdx.y * 128;
    const int n0 = blockIdx.x * 128;
    const int tid = threadIdx.x;
    const int tx = tid & 15, ty = tid >> 4;
    const int arow = tid >> 1, acol4 = (tid & 1) * 4;
    const int brow = tid >> 5, bcol4 = (tid & 31) * 4;
    float acc[8][8];
#pragma unroll
    for (int i = 0; i < 8; i++)
#pragma unroll
        for (int j = 0; j < 8; j++) acc[i][j] = 0.f;

    for (int k0 = 0; k0 < K; k0 += 8) {
        float4 av = *(const float4*)(A + (size_t)(m0 + arow) * lda + k0 + acol4);
        As[acol4+0][arow] = av.x; As[acol4+1][arow] = av.y;
        As[acol4+2][arow] = av.z; As[acol4+3][arow] = av.w;
        float4 bv = *(const float4*)(Bz + (size_t)(k0 + brow) * ldb + n0 + bcol4);
        *(float4*)&Bs[brow][bcol4] = bv;
        __syncthreads();
#pragma unroll
        for (int k = 0; k < 8; k++) {
            float ra[8], rb[8];
            *(float4*)&ra[0] = *(const float4*)&As[k][ty*8];
            *(float4*)&ra[4] = *(const float4*)&As[k][ty*8+4];
            *(float4*)&rb[0] = *(const float4*)&Bs[k][tx*8];
            *(float4*)&rb[4] = *(const float4*)&Bs[k][tx*8+4];
#pragma unroll
            for (int i = 0; i < 8; i++)
#pragma unroll
                for (int j = 0; j < 8; j++) acc[i][j] += ra[i]*rb[j];
        }
        __syncthreads();
    }
#pragma unroll
    for (int i = 0; i < 8; i++) {
        float* cr = C + (size_t)(m0 + ty*8 + i) * ldc + cbase + n0 + tx*8;
        *(float4*)cr       = make_float4(acc[i][0],acc[i][1],acc[i][2],acc[i][3]);
        *(float4*)(cr + 4) = make_float4(acc[i][4],acc[i][5],acc[i][6],acc[i][7]);
    }
}

// NT: B is [N,K] row-major (k contiguous)
__global__ __launch_bounds__(256, 2)
void sgemm_nt(const float* __restrict__ A, const float* __restrict__ B,
              float* __restrict__ C, int K, int lda, int ldb, int ldc)
{
    __shared__ float As[8][128];
    __shared__ float Bs[8][128];
    const int m0 = blockIdx.y * 128;
    const int n0 = blockIdx.x * 128;
    const int tid = threadIdx.x;
    const int tx = tid & 15, ty = tid >> 4;
    const int arow = tid >> 1, acol4 = (tid & 1) * 4;
    float acc[8][8];
#pragma unroll
    for (int i = 0; i < 8; i++)
#pragma unroll
        for (int j = 0; j < 8; j++) acc[i][j] = 0.f;

    for (int k0 = 0; k0 < K; k0 += 8) {
        float4 av = *(const float4*)(A + (size_t)(m0 + arow) * lda + k0 + acol4);
        As[acol4+0][arow] = av.x; As[acol4+1][arow] = av.y;
        As[acol4+2][arow] = av.z; As[acol4+3][arow] = av.w;
        float4 bw = *(const float4*)(B + (size_t)(n0 + arow) * ldb + k0 + acol4);
        Bs[acol4+0][arow] = bw.x; Bs[acol4+1][arow] = bw.y;
        Bs[acol4+2][arow] = bw.z; Bs[acol4+3][arow] = bw.w;
        __syncthreads();
#pragma unroll
        for (int k = 0; k < 8; k++) {
            float ra[8], rb[8];
            *(float4*)&ra[0] = *(const float4*)&As[k][ty*8];
            *(float4*)&ra[4] = *(const float4*)&As[k][ty*8+4];
            *(float4*)&rb[0] = *(const float4*)&Bs[k][tx*8];
            *(float4*)&rb[4] = *(const float4*)&Bs[k][tx*8+4];
#pragma unroll
            for (int i = 0; i < 8; i++)
#pragma unroll
                for (int j = 0; j < 8; j++) acc[i][j] += ra[i]*rb[j];
        }
        __syncthreads();
    }
#pragma unroll
    for (int i = 0; i < 8; i++) {
        float* cr = C + (size_t)(m0 + ty*8 + i) * ldc + n0 + tx*8;
        *(float4*)cr       = make_float4(acc[i][0],acc[i][1],acc[i][2],acc[i][3]);
        *(float4*)(cr + 4) = make_float4(acc[i][4],acc[i][5],acc[i][6],acc[i][7]);
    }
}

// ---------------- per-head RMSNorm + RoPE (H=256) ----------------
__global__ void qkv_post_kernel(float* __restrict__ buf, int ld,
                                const float* __restrict__ nscale,
                                const int* __restrict__ segpos,
                                int dorope)
{
    const int bt = blockIdx.x;
    const int head = blockIdx.y;
    const int h = threadIdx.x;
    float* p = buf + (size_t)bt * ld + head * HDIM;
    float v = p[h];
    __shared__ float red[8];
    __shared__ float nb[HDIM];
    float ss = v * v;
#pragma unroll
    for (int o = 16; o; o >>= 1) ss += __shfl_xor_sync(0xffffffffu, ss, o);
    if ((h & 31) == 0) red[h >> 5] = ss;
    __syncthreads();
    if (h < 32) {
        float t = (h < 8) ? red[h] : 0.f;
#pragma unroll
        for (int o = 4; o; o >>= 1) t += __shfl_xor_sync(0xffffffffu, t, o);
        if (h == 0) red[0] = t;
    }
    __syncthreads();
    float normed = v * rsqrtf(red[0] * (1.f/HDIM) + 1e-6f);
    if (nscale) normed *= (1.f + nscale[h]);
    if (dorope) {
        nb[h] = normed;
        __syncthreads();
        const int i = h & 127;
        // timescale = 10000^(i/128); compute via exp2f for accuracy
        const float ts = exp2f((float)i * (13.287712379549449f / 128.f));
        const float ang = (float)segpos[bt] / ts;
        float sn, cs;
        sincosf(ang, &sn, &cs);
        const float fi = nb[i], se = nb[i + 128];
        normed = (h < 128) ? (fi*cs - se*sn) : (se*cs + fi*sn);
    }
    p[h] = normed;
}

// ---------------- flash attention: 32 queries x 1 head per block ----------------
#define AT_TQ 32
#define AT_CS 32
#define AT_PAD 260
#define AT_SMEM ((3*AT_TQ*AT_PAD + AT_TQ*33 + 3*AT_TQ + 2*AT_TQ) * 4)

__global__ __launch_bounds__(256, 1)
void attn_kernel(const float* __restrict__ qb, const float* __restrict__ kb,
                 const float* __restrict__ vb, const int* __restrict__ segpos,
                 float* __restrict__ enc)
{
    const int b = blockIdx.z, n = blockIdx.y, tile = blockIdx.x;
    const int t0 = tile * AT_TQ;
    const int kk = n / GQA;
    extern __shared__ float sm[];
    float* Qs = sm;                         // 32 x 260
    float* Ks = Qs + AT_TQ*AT_PAD;          // 32 x 260
    float* Vs = Ks + AT_CS*AT_PAD;          // 32 x 260
    float* Ps = Vs + AT_CS*AT_PAD;          // 32 x 33
    float* mrow = Ps + AT_TQ*33;
    float* lrow = mrow + AT_TQ;
    float* srow = lrow + AT_TQ;
    int*   pts  = (int*)(srow + AT_TQ);
    int*   pss  = pts + AT_TQ;

    const int tid = threadIdx.x;
    const int lane = tid & 31, warp = tid >> 5;
    const int hq = tid & 63, ig = tid >> 6;

    for (int idx = tid; idx < AT_TQ*HDIM; idx += 256) {
        const int r = idx >> 8, h = idx & 255;
        Qs[r*AT_PAD + h] = qb[((size_t)(b*TSEQ + t0 + r))*(NHEADS*HDIM) + n*HDIM + h];
    }
    if (tid < AT_TQ) {
        pts[tid] = segpos[b*TSEQ + t0 + tid];
        mrow[tid] = -1e30f; lrow[tid] = 0.f;
    }
    float acc[8][4];
#pragma unroll
    for (int i = 0; i < 8; i++)
#pragma unroll
        for (int j = 0; j < 4; j++) acc[i][j] = 0.f;

    int s_begin = t0 - (WINDOW - 1);
    if (s_begin < 0) s_begin = 0;
    s_begin &= ~(AT_CS - 1);

    for (int s0 = s_begin; s0 < t0 + AT_TQ; s0 += AT_CS) {
        __syncthreads();
        for (int idx = tid; idx < AT_CS*HDIM; idx += 256) {
            const int r = idx >> 8, h = idx & 255;
            const size_t src = ((size_t)(b*TSEQ + s0 + r))*(KVHEADS*HDIM) + kk*HDIM + h;
            Ks[r*AT_PAD + h] = kb[src];
            Vs[r*AT_PAD + h] = vb[src];
        }
        if (tid < AT_CS) pss[tid] = segpos[b*TSEQ + s0 + tid];
        __syncthreads();

        // logits: warp -> rows {warp, warp+8, warp+16, warp+24}, lane -> key j
        float sv[4] = {0.f, 0.f, 0.f, 0.f};
        const float4* K4 = (const float4*)(Ks + lane*AT_PAD);
#pragma unroll 8
        for (int h4 = 0; h4 < 64; h4++) {
            const float4 kvv = K4[h4];
#pragma unroll
            for (int rr = 0; rr < 4; rr++) {
                const float4 qv = *(const float4*)(Qs + (warp + rr*8)*AT_PAD + h4*4);
                sv[rr] += qv.x*kvv.x + qv.y*kvv.y + qv.z*kvv.z + qv.w*kvv.w;
            }
        }
        const int ps = pss[lane];
        const int sg = s0 + lane;
#pragma unroll
        for (int rr = 0; rr < 4; rr++) {
            const int r = warp + rr*8;
            const int tg = t0 + r;
            const int pt = pts[r];
            float s = tanhf(sv[rr] * (1.f/SOFTCAP)) * SOFTCAP;
            const bool valid = (sg <= tg) && (ps > pt - WINDOW) && (ps < pt + WINDOW);
            if (!valid) s = -1e30f;
            float mc = s;
#pragma unroll
            for (int o = 16; o; o >>= 1) mc = fmaxf(mc, __shfl_xor_sync(0xffffffffu, mc, o));
            const float mold = mrow[r];
            const float mnew = fmaxf(mold, mc);
            const float p = __expf(s - mnew);
            float pr = p;
#pragma unroll
            for (int o = 16; o; o >>= 1) pr += __shfl_xor_sync(0xffffffffu, pr, o);
            Ps[r*33 + lane] = p;
            if (lane == 0) {
                const float sc = __expf(mold - mnew);
                srow[r] = sc;
                lrow[r] = lrow[r]*sc + pr;
                mrow[r] = mnew;
            }
        }
        __syncthreads();

        // O update: thread owns rows ig*8..ig*8+7, cols hq*4..hq*4+3
#pragma unroll
        for (int rr = 0; rr < 8; rr++) {
            const float sc = srow[ig*8 + rr];
            acc[rr][0]*=sc; acc[rr][1]*=sc; acc[rr][2]*=sc; acc[rr][3]*=sc;
        }
#pragma unroll 4
        for (int j = 0; j < AT_CS; j++) {
            const float4 vv = *(const float4*)(Vs + j*AT_PAD + hq*4);
#pragma unroll
            for (int rr = 0; rr < 8; rr++) {
                const float p = Ps[(ig*8+rr)*33 + j];
                acc[rr][0] += p*vv.x; acc[rr][1] += p*vv.y;
                acc[rr][2] += p*vv.z; acc[rr][3] += p*vv.w;
            }
        }
    }
    __syncthreads();
#pragma unroll
    for (int rr = 0; rr < 8; rr++) {
        const int r = ig*8 + rr;
        const float inv = 1.f / lrow[r];
        float4 o = make_float4(acc[rr][0]*inv, acc[rr][1]*inv, acc[rr][2]*inv, acc[rr][3]*inv);
        *(float4*)(enc + ((size_t)(b*TSEQ + t0 + r))*(NHEADS*HDIM) + n*HDIM + hq*4) = o;
    }
}

// ---------------- gated GELU ----------------
__global__ void act_kernel(const float* __restrict__ gates, float* __restrict__ act)
{
    const int i = blockIdx.x * blockDim.x + threadIdx.x;
    if (i >= BT*FFDIM) return;
    const int bt = i >> 13;          // /8192
    const int f = i & (FFDIM - 1);
    const float x0 = gates[(size_t)bt*(2*FFDIM) + f];
    const float x1 = gates[(size_t)bt*(2*FFDIM) + FFDIM + f];
    const float g = 0.5f*x0*(1.f + tanhf(0.7978845608028654f*(x0 + 0.044715f*x0*x0*x0)));
    act[i] = g * x1;
}

// ---------------- launch ----------------
static float* symaddr(const void* sym) {
    void* p = nullptr;
    cudaGetSymbolAddress(&p, sym);
    return (float*)p;
}

extern "C" void kernel_launch(void* const* d_in, const int* in_sizes, int n_in,
                              void* d_out, int out_size)
{
    const float* x        = (const float*)d_in[0];
    const int*   segpos   = (const int*)  d_in[1];
    const float* w_q      = (const float*)d_in[7];
    const float* w_kv     = (const float*)d_in[8];
    const float* w_avec   = (const float*)d_in[9];
    const float* q_norm   = (const float*)d_in[10];
    const float* k_norm   = (const float*)d_in[11];
    const float* pre_attn = (const float*)d_in[12];
    const float* post_attn= (const float*)d_in[13];
    const float* pre_ffw  = (const float*)d_in[14];
    const float* post_ffw = (const float*)d_in[15];
    const float* w_gating = (const float*)d_in[16];
    const float* w_linear = (const float*)d_in[17];
    const float* skip     = (const float*)d_in[18];

    float* h    = symaddr(g_h);
    float* q    = symaddr(g_q);
    float* k    = symaddr(g_k);
    float* v    = symaddr(g_v);
    float* enc  = symaddr(g_enc);
    float* aproj= symaddr(g_aproj);
    float* ares = symaddr(g_ares);
    float* ffin = symaddr(g_ffin);
    float* gates= symaddr(g_gates);
    float* act  = symaddr(g_act);
    float* fout = symaddr(g_fout);

    // 1) pre-attn RMSNorm
    rows_norm_kernel<<<BT, 256>>>(x, pre_attn, nullptr, nullptr, h);

    // 2) projections  (per-head GEMMs via grid.z)
    sgemm_nn<<<dim3(HDIM/128, BT/128, NHEADS), 256>>>(h, w_q, q,
        DMODEL, DMODEL, HDIM, NHEADS*HDIM, DMODEL*HDIM, HDIM);
    sgemm_nn<<<dim3(HDIM/128, BT/128, KVHEADS), 256>>>(h, w_kv, k,
        DMODEL, DMODEL, HDIM, KVHEADS*HDIM, DMODEL*HDIM, HDIM);
    sgemm_nn<<<dim3(HDIM/128, BT/128, KVHEADS), 256>>>(h, w_kv + (size_t)KVHEADS*DMODEL*HDIM, v,
        DMODEL, DMODEL, HDIM, KVHEADS*HDIM, DMODEL*HDIM, HDIM);

    // 3) q/k/v norms + rope
    qkv_post_kernel<<<dim3(BT, NHEADS), 256>>>(q, NHEADS*HDIM, q_norm, segpos, 1);
    qkv_post_kernel<<<dim3(BT, KVHEADS), 256>>>(k, KVHEADS*HDIM, k_norm, segpos, 1);
    qkv_post_kernel<<<dim3(BT, KVHEADS), 256>>>(v, KVHEADS*HDIM, nullptr, segpos, 0);

    // 4) attention
    cudaFuncSetAttribute(attn_kernel, cudaFuncAttributeMaxDynamicSharedMemorySize, AT_SMEM);
    attn_kernel<<<dim3(TSEQ/AT_TQ, NHEADS, BATCH), 256, AT_SMEM>>>(q, k, v, segpos, enc);

    // 5) attn output projection
    sgemm_nn<<<dim3(DMODEL/128, BT/128, 1), 256>>>(enc, w_avec, aproj,
        NHEADS*HDIM, NHEADS*HDIM, DMODEL, DMODEL, 0, 0);

    // 6) post-attn norm + residual:  ares = x*skip + rmsnorm(aproj, post_attn)
    rows_norm_kernel<<<BT, 256>>>(aproj, post_attn, x, skip, ares);

    // 7) pre-ffw norm
    rows_norm_kernel<<<BT, 256>>>(ares, pre_ffw, nullptr, nullptr, ffin);

    // 8) gating GEMM (both c=0,1 in one 16384-wide NT GEMM)
    sgemm_nt<<<dim3((2*FFDIM)/128, BT/128, 1), 256>>>(ffin, w_gating, gates,
        DMODEL, DMODEL, DMODEL, 2*FFDIM);

    // 9) gated gelu
    act_kernel<<<(BT*FFDIM + 255)/256, 256>>>(gates, act);

    // 10) down projection
    sgemm_nn<<<dim3(DMODEL/128, BT/128, 1), 256>>>(act, w_linear, fout,
        FFDIM, FFDIM, DMODEL, DMODEL, 0, 0);

    // 11) final: out = ares + rmsnorm(fout, post_ffw)
    rows_norm_kernel<<<BT, 256>>>(fout, post_ffw, ares, nullptr, (float*)d_out);
}

// round 7
// speedup vs baseline: 1.4143x; 1.4143x over previous
#include <cuda_runtime.h>
#include <cuda_bf16.h>
#include <stdint.h>
#include <math.h>

// ---------------- problem constants ----------------
#define BATCH 2
#define TSEQ 2048
#define BT (BATCH*TSEQ)          // 4096
#define DMODEL 2048
#define NHEADS 8
#define KVHEADS 4
#define GQA (NHEADS/KVHEADS)     // 2
#define HDIM 256
#define FFDIM 8192
#define WINDOW 1024
#define SOFTCAP 50.0f

typedef unsigned int u32;

// ---------------- scratch (no cudaMalloc allowed) ----------------
__device__ float g_h    [(size_t)BT*DMODEL];
__device__ float g_q    [(size_t)BT*NHEADS*HDIM];
__device__ float g_k    [(size_t)BT*KVHEADS*HDIM];
__device__ float g_v    [(size_t)BT*KVHEADS*HDIM];
__device__ float g_enc  [(size_t)BT*NHEADS*HDIM];
__device__ float g_aproj[(size_t)BT*DMODEL];
__device__ float g_ares [(size_t)BT*DMODEL];
__device__ float g_ffin [(size_t)BT*DMODEL];
__device__ float g_gates[(size_t)BT*2*FFDIM];
__device__ float g_act  [(size_t)BT*FFDIM];
__device__ float g_fout [(size_t)BT*DMODEL];

// ---------------- row-wise RMSNorm (D=2048), optional residual ----------------
__global__ void rows_norm_kernel(const float* __restrict__ in,
                                 const float* __restrict__ scale,
                                 const float* __restrict__ resid,
                                 const float* __restrict__ skip,
                                 float* __restrict__ out)
{
    const int row = blockIdx.x;
    const int tid = threadIdx.x;
    const size_t base = (size_t)row * DMODEL;
    float vals[8];
    float ss = 0.f;
#pragma unroll
    for (int i = 0; i < 8; i++) {
        float v = in[base + tid + i*256];
        vals[i] = v; ss += v*v;
    }
    __shared__ float red[8];
#pragma unroll
    for (int o = 16; o; o >>= 1) ss += __shfl_xor_sync(0xffffffffu, ss, o);
    if ((tid & 31) == 0) red[tid >> 5] = ss;
    __syncthreads();
    if (tid < 32) {
        float t = (tid < 8) ? red[tid] : 0.f;
#pragma unroll
        for (int o = 4; o; o >>= 1) t += __shfl_xor_sync(0xffffffffu, t, o);
        if (tid == 0) red[0] = t;
    }
    __syncthreads();
    const float inv = rsqrtf(red[0] * (1.f/DMODEL) + 1e-6f);
    const float sk = skip ? skip[0] : 1.f;
#pragma unroll
    for (int i = 0; i < 8; i++) {
        const int d = tid + i*256;
        float o = vals[i] * inv * (1.f + (scale ? scale[d] : 0.f));
        if (resid) o += resid[base + d] * sk;
        out[base + d] = o;
    }
}

// ---------------- 3xTF32 tensor-core GEMM 128x128x16, 256 thr, mma.m16n8k8 -----
// Each fp32 input x is split x = hi + lo (both tf32).  acc += hi*hi + hi*lo + lo*hi
// drops only the ~2^-24 lo*lo term -> near-fp32 accuracy on the tensor pipe.
__device__ __forceinline__ u32 f2tf(float x){
    u32 r; asm("cvt.rna.tf32.f32 %0, %1;" : "=r"(r) : "f"(x)); return r;
}
__device__ __forceinline__ void split_tf(float x, u32& hi, u32& lo){
    hi = f2tf(x);
    lo = f2tf(x - __uint_as_float(hi));
}

#define MMA3(d, ah, al, bh, bl)                                                  \
    asm volatile("mma.sync.aligned.m16n8k8.row.col.f32.tf32.tf32.f32 "           \
        "{%0,%1,%2,%3}, {%4,%5,%6,%7}, {%8,%9}, {%0,%1,%2,%3};"                  \
        : "+f"(d[0]), "+f"(d[1]), "+f"(d[2]), "+f"(d[3])                         \
        : "r"(ah[0]), "r"(ah[1]), "r"(ah[2]), "r"(ah[3]), "r"(bh[0]), "r"(bh[1]));\
    asm volatile("mma.sync.aligned.m16n8k8.row.col.f32.tf32.tf32.f32 "           \
        "{%0,%1,%2,%3}, {%4,%5,%6,%7}, {%8,%9}, {%0,%1,%2,%3};"                  \
        : "+f"(d[0]), "+f"(d[1]), "+f"(d[2]), "+f"(d[3])                         \
        : "r"(ah[0]), "r"(ah[1]), "r"(ah[2]), "r"(ah[3]), "r"(bl[0]), "r"(bl[1]));\
    asm volatile("mma.sync.aligned.m16n8k8.row.col.f32.tf32.tf32.f32 "           \
        "{%0,%1,%2,%3}, {%4,%5,%6,%7}, {%8,%9}, {%0,%1,%2,%3};"                  \
        : "+f"(d[0]), "+f"(d[1]), "+f"(d[2]), "+f"(d[3])                         \
        : "r"(al[0]), "r"(al[1]), "r"(al[2]), "r"(al[3]), "r"(bh[0]), "r"(bh[1]));

// LAYB: 0 = NN (B[k][n] row-major), 1 = NT (B[n][k] row-major)
// Smem rows hold hi and lo halves side by side:
//   A  : [2][128][36]  hi cols 0..15, lo cols 16..31, 4 pad
//   BNN: [2][16][260]  hi n 0..127,  lo n 128..255, 4 pad
//   BNT: [2][128][36]  like A
template<int LAYB>
__global__ __launch_bounds__(256, 2)
void gemm_3xtf32(const float* __restrict__ A, const float* __restrict__ B,
                 float* __restrict__ C, int K, int lda, int ldb, int ldc,
                 size_t wstride_z, int cstride_z)
{
    extern __shared__ u32 smemu[];
    u32* As = smemu;                      // [2][128][36]
    u32* Bs = smemu + 2*128*36;

    const int tid  = threadIdx.x;
    const int lane = tid & 31;
    const int warp = tid >> 5;
    const int wm = (warp >> 2) * 64;      // warps 2x4, warp tile 64x32
    const int wn = (warp & 3) * 32;
    const int qr = lane >> 2, qc = lane & 3;
    const int m0 = blockIdx.y * 128, n0 = blockIdx.x * 128;
    const float* Ag = A + (size_t)m0 * lda;
    const float* Bg = B + (size_t)blockIdx.z * wstride_z;

    float acc[4][4][4];
#pragma unroll
    for (int i = 0; i < 4; i++)
#pragma unroll
        for (int j = 0; j < 4; j++) {
            acc[i][j][0]=0.f; acc[i][j][1]=0.f; acc[i][j][2]=0.f; acc[i][j][3]=0.f;
        }

    auto stage = [&](int k0, int buf) {
        u32* Ab = As + buf*(128*36);
        // A tile: 128 rows x 16 k = 512 float4 loads, 2 per thread
#pragma unroll
        for (int i = 0; i < 2; i++) {
            const int idx = tid + i*256;
            const int row = idx >> 2, kg = (idx & 3) * 4;
            float4 v = *(const float4*)(Ag + (size_t)row*lda + k0 + kg);
            u32 h0,l0,h1,l1,h2,l2,h3,l3;
            split_tf(v.x,h0,l0); split_tf(v.y,h1,l1);
            split_tf(v.z,h2,l2); split_tf(v.w,h3,l3);
            u32* r = Ab + row*36 + kg;
            r[0]=h0; r[1]=h1; r[2]=h2; r[3]=h3;
            r[16]=l0; r[17]=l1; r[18]=l2; r[19]=l3;
        }
        if (LAYB == 0) {
            u32* Bb = Bs + buf*(16*260);
            // B tile: 16 k-rows x 128 n = 512 float4, 2 per thread
#pragma unroll
            for (int i = 0; i < 2; i++) {
                const int idx = tid + i*256;
                const int row = idx >> 5, nn = (idx & 31) * 4;
                float4 v = *(const float4*)(Bg + (size_t)(k0 + row)*ldb + n0 + nn);
                u32 h0,l0,h1,l1,h2,l2,h3,l3;
                split_tf(v.x,h0,l0); split_tf(v.y,h1,l1);
                split_tf(v.z,h2,l2); split_tf(v.w,h3,l3);
                u32* r = Bb + row*260 + nn;
                r[0]=h0; r[1]=h1; r[2]=h2; r[3]=h3;
                r[128]=l0; r[129]=l1; r[130]=l2; r[131]=l3;
            }
        } else {
            u32* Bb = Bs + buf*(128*36);
#pragma unroll
            for (int i = 0; i < 2; i++) {
                const int idx = tid + i*256;
                const int row = idx >> 2, kg = (idx & 3) * 4;
                float4 v = *(const float4*)(Bg + (size_t)(n0 + row)*ldb + k0 + kg);
                u32 h0,l0,h1,l1,h2,l2,h3,l3;
                split_tf(v.x,h0,l0); split_tf(v.y,h1,l1);
                split_tf(v.z,h2,l2); split_tf(v.w,h3,l3);
                u32* r = Bb + row*36 + kg;
                r[0]=h0; r[1]=h1; r[2]=h2; r[3]=h3;
                r[16]=l0; r[17]=l1; r[18]=l2; r[19]=l3;
            }
        }
    };

    const int nIt = K / 16;
    stage(0, 0);
    __syncthreads();

    for (int it = 0; it < nIt; it++) {
        const int cur = it & 1;
        if (it + 1 < nIt) stage((it + 1) * 16, cur ^ 1);
        const u32* Ab = As + cur*(128*36);
        const u32* Bb = Bs + cur*((LAYB == 0) ? (16*260) : (128*36));
#pragma unroll
        for (int ks = 0; ks < 2; ks++) {
            const int kk = ks * 8;
            u32 ah[4][4], al[4][4];
#pragma unroll
            for (int mf = 0; mf < 4; mf++) {
                const u32* p = Ab + (wm + mf*16 + qr)*36 + kk + qc;
                ah[mf][0] = p[0];       ah[mf][2] = p[4];
                ah[mf][1] = p[8*36];    ah[mf][3] = p[8*36 + 4];
                al[mf][0] = p[16];      al[mf][2] = p[20];
                al[mf][1] = p[8*36+16]; al[mf][3] = p[8*36 + 20];
            }
#pragma unroll
            for (int nf = 0; nf < 4; nf++) {
                u32 bh[2], bl[2];
                if (LAYB == 0) {
                    const u32* p = Bb + (kk + qc)*260 + wn + nf*8 + qr;
                    bh[0] = p[0];   bh[1] = p[4*260];
                    bl[0] = p[128]; bl[1] = p[4*260 + 128];
                } else {
                    const u32* p = Bb + (wn + nf*8 + qr)*36 + kk + qc;
                    bh[0] = p[0];  bh[1] = p[4];
                    bl[0] = p[16]; bl[1] = p[20];
                }
#pragma unroll
                for (int mf = 0; mf < 4; mf++) {
                    MMA3(acc[mf][nf], ah[mf], al[mf], bh, bl);
                }
            }
        }
        __syncthreads();
    }

    const int cb = blockIdx.z * cstride_z;
#pragma unroll
    for (int mf = 0; mf < 4; mf++) {
        const int r = m0 + wm + mf*16 + qr;
#pragma unroll
        for (int nf = 0; nf < 4; nf++) {
            const int c = cb + n0 + wn + nf*8 + 2*qc;
            *(float2*)(C + (size_t)r*ldc + c)     = make_float2(acc[mf][nf][0], acc[mf][nf][1]);
            *(float2*)(C + (size_t)(r+8)*ldc + c) = make_float2(acc[mf][nf][2], acc[mf][nf][3]);
        }
    }
}

// ---------------- per-head RMSNorm + RoPE (H=256) ----------------
__global__ void qkv_post_kernel(float* __restrict__ buf, int ld,
                                const float* __restrict__ nscale,
                                const int* __restrict__ segpos,
                                int dorope)
{
    const int bt = blockIdx.x;
    const int head = blockIdx.y;
    const int h = threadIdx.x;
    float* p = buf + (size_t)bt * ld + head * HDIM;
    float v = p[h];
    __shared__ float red[8];
    __shared__ float nb[HDIM];
    float ss = v * v;
#pragma unroll
    for (int o = 16; o; o >>= 1) ss += __shfl_xor_sync(0xffffffffu, ss, o);
    if ((h & 31) == 0) red[h >> 5] = ss;
    __syncthreads();
    if (h < 32) {
        float t = (h < 8) ? red[h] : 0.f;
#pragma unroll
        for (int o = 4; o; o >>= 1) t += __shfl_xor_sync(0xffffffffu, t, o);
        if (h == 0) red[0] = t;
    }
    __syncthreads();
    float normed = v * rsqrtf(red[0] * (1.f/HDIM) + 1e-6f);
    if (nscale) normed *= (1.f + nscale[h]);
    if (dorope) {
        nb[h] = normed;
        __syncthreads();
        const int i = h & 127;
        const float ts = exp2f((float)i * (13.287712379549449f / 128.f));
        const float ang = (float)segpos[bt] / ts;
        float sn, cs;
        sincosf(ang, &sn, &cs);
        const float fi = nb[i], se = nb[i + 128];
        normed = (h < 128) ? (fi*cs - se*sn) : (se*cs + fi*sn);
    }
    p[h] = normed;
}

// ---------------- flash attention: 32 queries x 1 head per block ----------------
#define AT_TQ 32
#define AT_CS 32
#define AT_PAD 260
#define AT_SMEM ((3*AT_TQ*AT_PAD + AT_TQ*33 + 3*AT_TQ + 2*AT_TQ) * 4)

__global__ __launch_bounds__(256, 1)
void attn_kernel(const float* __restrict__ qb, const float* __restrict__ kb,
                 const float* __restrict__ vb, const int* __restrict__ segpos,
                 float* __restrict__ enc)
{
    const int b = blockIdx.z, n = blockIdx.y, tile = blockIdx.x;
    const int t0 = tile * AT_TQ;
    const int kk = n / GQA;
    extern __shared__ float sm[];
    float* Qs = sm;
    float* Ks = Qs + AT_TQ*AT_PAD;
    float* Vs = Ks + AT_CS*AT_PAD;
    float* Ps = Vs + AT_CS*AT_PAD;
    float* mrow = Ps + AT_TQ*33;
    float* lrow = mrow + AT_TQ;
    float* srow = lrow + AT_TQ;
    int*   pts  = (int*)(srow + AT_TQ);
    int*   pss  = pts + AT_TQ;

    const int tid = threadIdx.x;
    const int lane = tid & 31, warp = tid >> 5;
    const int hq = tid & 63, ig = tid >> 6;

    for (int idx = tid; idx < AT_TQ*HDIM; idx += 256) {
        const int r = idx >> 8, h = idx & 255;
        Qs[r*AT_PAD + h] = qb[((size_t)(b*TSEQ + t0 + r))*(NHEADS*HDIM) + n*HDIM + h];
    }
    if (tid < AT_TQ) {
        pts[tid] = segpos[b*TSEQ + t0 + tid];
        mrow[tid] = -1e30f; lrow[tid] = 0.f;
    }
    float acc[8][4];
#pragma unroll
    for (int i = 0; i < 8; i++)
#pragma unroll
        for (int j = 0; j < 4; j++) acc[i][j] = 0.f;

    int s_begin = t0 - (WINDOW - 1);
    if (s_begin < 0) s_begin = 0;
    s_begin &= ~(AT_CS - 1);

    for (int s0 = s_begin; s0 < t0 + AT_TQ; s0 += AT_CS) {
        __syncthreads();
        for (int idx = tid; idx < AT_CS*HDIM; idx += 256) {
            const int r = idx >> 8, h = idx & 255;
            const size_t src = ((size_t)(b*TSEQ + s0 + r))*(KVHEADS*HDIM) + kk*HDIM + h;
            Ks[r*AT_PAD + h] = kb[src];
            Vs[r*AT_PAD + h] = vb[src];
        }
        if (tid < AT_CS) pss[tid] = segpos[b*TSEQ + s0 + tid];
        __syncthreads();

        float sv[4] = {0.f, 0.f, 0.f, 0.f};
        const float4* K4 = (const float4*)(Ks + lane*AT_PAD);
#pragma unroll 8
        for (int h4 = 0; h4 < 64; h4++) {
            const float4 kvv = K4[h4];
#pragma unroll
            for (int rr = 0; rr < 4; rr++) {
                const float4 qv = *(const float4*)(Qs + (warp + rr*8)*AT_PAD + h4*4);
                sv[rr] += qv.x*kvv.x + qv.y*kvv.y + qv.z*kvv.z + qv.w*kvv.w;
            }
        }
        const int ps = pss[lane];
        const int sg = s0 + lane;
#pragma unroll
        for (int rr = 0; rr < 4; rr++) {
            const int r = warp + rr*8;
            const int tg = t0 + r;
            const int pt = pts[r];
            float s = tanhf(sv[rr] * (1.f/SOFTCAP)) * SOFTCAP;
            const bool valid = (sg <= tg) && (ps > pt - WINDOW) && (ps < pt + WINDOW);
            if (!valid) s = -1e30f;
            float mc = s;
#pragma unroll
            for (int o = 16; o; o >>= 1) mc = fmaxf(mc, __shfl_xor_sync(0xffffffffu, mc, o));
            const float mold = mrow[r];
            const float mnew = fmaxf(mold, mc);
            const float p = __expf(s - mnew);
            float pr = p;
#pragma unroll
            for (int o = 16; o; o >>= 1) pr += __shfl_xor_sync(0xffffffffu, pr, o);
            Ps[r*33 + lane] = p;
            if (lane == 0) {
                const float sc = __expf(mold - mnew);
                srow[r] = sc;
                lrow[r] = lrow[r]*sc + pr;
                mrow[r] = mnew;
            }
        }
        __syncthreads();

#pragma unroll
        for (int rr = 0; rr < 8; rr++) {
            const float sc = srow[ig*8 + rr];
            acc[rr][0]*=sc; acc[rr][1]*=sc; acc[rr][2]*=sc; acc[rr][3]*=sc;
        }
#pragma unroll 4
        for (int j = 0; j < AT_CS; j++) {
            const float4 vv = *(const float4*)(Vs + j*AT_PAD + hq*4);
#pragma unroll
            for (int rr = 0; rr < 8; rr++) {
                const float p = Ps[(ig*8+rr)*33 + j];
                acc[rr][0] += p*vv.x; acc[rr][1] += p*vv.y;
                acc[rr][2] += p*vv.z; acc[rr][3] += p*vv.w;
            }
        }
    }
    __syncthreads();
#pragma unroll
    for (int rr = 0; rr < 8; rr++) {
        const int r = ig*8 + rr;
        const float inv = 1.f / lrow[r];
        float4 o = make_float4(acc[rr][0]*inv, acc[rr][1]*inv, acc[rr][2]*inv, acc[rr][3]*inv);
        *(float4*)(enc + ((size_t)(b*TSEQ + t0 + r))*(NHEADS*HDIM) + n*HDIM + hq*4) = o;
    }
}

// ---------------- gated GELU ----------------
__global__ void act_kernel(const float* __restrict__ gates, float* __restrict__ act)
{
    const int i = blockIdx.x * blockDim.x + threadIdx.x;
    if (i >= BT*FFDIM) return;
    const int bt = i >> 13;
    const int f = i & (FFDIM - 1);
    const float x0 = gates[(size_t)bt*(2*FFDIM) + f];
    const float x1 = gates[(size_t)bt*(2*FFDIM) + FFDIM + f];
    const float g = 0.5f*x0*(1.f + tanhf(0.7978845608028654f*(x0 + 0.044715f*x0*x0*x0)));
    act[i] = g * x1;
}

// ---------------- launch ----------------
static float* symaddr(const void* sym) {
    void* p = nullptr;
    cudaGetSymbolAddress(&p, sym);
    return (float*)p;
}

#define SMEM_NN ((2*128*36 + 2*16*260) * 4)
#define SMEM_NT ((2*128*36 + 2*128*36) * 4)

extern "C" void kernel_launch(void* const* d_in, const int* in_sizes, int n_in,
                              void* d_out, int out_size)
{
    const float* x        = (const float*)d_in[0];
    const int*   segpos   = (const int*)  d_in[1];
    const float* w_q      = (const float*)d_in[7];
    const float* w_kv     = (const float*)d_in[8];
    const float* w_avec   = (const float*)d_in[9];
    const float* q_norm   = (const float*)d_in[10];
    const float* k_norm   = (const float*)d_in[11];
    const float* pre_attn = (const float*)d_in[12];
    const float* post_attn= (const float*)d_in[13];
    const float* pre_ffw  = (const float*)d_in[14];
    const float* post_ffw = (const float*)d_in[15];
    const float* w_gating = (const float*)d_in[16];
    const float* w_linear = (const float*)d_in[17];
    const float* skip     = (const float*)d_in[18];

    float* h    = symaddr(g_h);
    float* q    = symaddr(g_q);
    float* k    = symaddr(g_k);
    float* v    = symaddr(g_v);
    float* enc  = symaddr(g_enc);
    float* aproj= symaddr(g_aproj);
    float* ares = symaddr(g_ares);
    float* ffin = symaddr(g_ffin);
    float* gates= symaddr(g_gates);
    float* act  = symaddr(g_act);
    float* fout = symaddr(g_fout);

    cudaFuncSetAttribute(gemm_3xtf32<0>, cudaFuncAttributeMaxDynamicSharedMemorySize, SMEM_NN);
    cudaFuncSetAttribute(gemm_3xtf32<1>, cudaFuncAttributeMaxDynamicSharedMemorySize, SMEM_NT);
    cudaFuncSetAttribute(attn_kernel,   cudaFuncAttributeMaxDynamicSharedMemorySize, AT_SMEM);

    // 1) pre-attn RMSNorm
    rows_norm_kernel<<<BT, 256>>>(x, pre_attn, nullptr, nullptr, h);

    // 2) projections (3xTF32 tensor cores, per-head via grid.z)
    gemm_3xtf32<0><<<dim3(HDIM/128, BT/128, NHEADS), 256, SMEM_NN>>>(
        h, w_q, q, DMODEL, DMODEL, HDIM, NHEADS*HDIM, (size_t)DMODEL*HDIM, HDIM);
    gemm_3xtf32<0><<<dim3(HDIM/128, BT/128, KVHEADS), 256, SMEM_NN>>>(
        h, w_kv, k, DMODEL, DMODEL, HDIM, KVHEADS*HDIM, (size_t)DMODEL*HDIM, HDIM);
    gemm_3xtf32<0><<<dim3(HDIM/128, BT/128, KVHEADS), 256, SMEM_NN>>>(
        h, w_kv + (size_t)KVHEADS*DMODEL*HDIM, v, DMODEL, DMODEL, HDIM, KVHEADS*HDIM,
        (size_t)DMODEL*HDIM, HDIM);

    // 3) q/k/v norms + rope
    qkv_post_kernel<<<dim3(BT, NHEADS), 256>>>(q, NHEADS*HDIM, q_norm, segpos, 1);
    qkv_post_kernel<<<dim3(BT, KVHEADS), 256>>>(k, KVHEADS*HDIM, k_norm, segpos, 1);
    qkv_post_kernel<<<dim3(BT, KVHEADS), 256>>>(v, KVHEADS*HDIM, nullptr, segpos, 0);

    // 4) attention
    attn_kernel<<<dim3(TSEQ/AT_TQ, NHEADS, BATCH), 256, AT_SMEM>>>(q, k, v, segpos, enc);

    // 5) attn output projection
    gemm_3xtf32<0><<<dim3(DMODEL/128, BT/128, 1), 256, SMEM_NN>>>(
        enc, w_avec, aproj, NHEADS*HDIM, NHEADS*HDIM, DMODEL, DMODEL, 0, 0);

    // 6) post-attn norm + residual
    rows_norm_kernel<<<BT, 256>>>(aproj, post_attn, x, skip, ares);

    // 7) pre-ffw norm
    rows_norm_kernel<<<BT, 256>>>(ares, pre_ffw, nullptr, nullptr, ffin);

    // 8) gating GEMM (NT, both gates in one 16384-wide GEMM)
    gemm_3xtf32<1><<<dim3((2*FFDIM)/128, BT/128, 1), 256, SMEM_NT>>>(
        ffin, w_gating, gates, DMODEL, DMODEL, DMODEL, 2*FFDIM, 0, 0);

    // 9) gated gelu
    act_kernel<<<(BT*FFDIM + 255)/256, 256>>>(gates, act);

    // 10) down projection
    gemm_3xtf32<0><<<dim3(DMODEL/128, BT/128, 1), 256, SMEM_NN>>>(
        act, w_linear, fout, FFDIM, FFDIM, DMODEL, DMODEL, 0, 0);

    // 11) final: out = ares + rmsnorm(fout, post_ffw)
    rows_norm_kernel<<<BT, 256>>>(fout, post_ffw, ares, nullptr, (float*)d_out);
}

// round 8
// speedup vs baseline: 2.2186x; 1.5686x over previous
#include <cuda_runtime.h>
#include <cuda_bf16.h>
#include <stdint.h>
#include <math.h>

// ---------------- problem constants ----------------
#define BATCH 2
#define TSEQ 2048
#define BT (BATCH*TSEQ)          // 4096
#define DMODEL 2048
#define NHEADS 8
#define KVHEADS 4
#define GQA (NHEADS/KVHEADS)     // 2
#define HDIM 256
#define FFDIM 8192
#define WINDOW 1024
#define SOFTCAP 50.0f

typedef unsigned int u32;
typedef unsigned short u16;

// ---------------- scratch (no cudaMalloc allowed) ----------------
__device__ float g_h    [(size_t)BT*DMODEL];
__device__ float g_q    [(size_t)BT*NHEADS*HDIM];
__device__ float g_k    [(size_t)BT*KVHEADS*HDIM];
__device__ float g_v    [(size_t)BT*KVHEADS*HDIM];
__device__ float g_enc  [(size_t)BT*NHEADS*HDIM];
__device__ float g_aproj[(size_t)BT*DMODEL];
__device__ float g_ares [(size_t)BT*DMODEL];
__device__ float g_ffin [(size_t)BT*DMODEL];
__device__ float g_gates[(size_t)BT*2*FFDIM];
__device__ float g_act  [(size_t)BT*FFDIM];
__device__ float g_fout [(size_t)BT*DMODEL];

// ---------------- row-wise RMSNorm (D=2048), optional residual ----------------
__global__ void rows_norm_kernel(const float* __restrict__ in,
                                 const float* __restrict__ scale,
                                 const float* __restrict__ resid,
                                 const float* __restrict__ skip,
                                 float* __restrict__ out)
{
    const int row = blockIdx.x;
    const int tid = threadIdx.x;
    const size_t base = (size_t)row * DMODEL;
    float vals[8];
    float ss = 0.f;
#pragma unroll
    for (int i = 0; i < 8; i++) {
        float v = in[base + tid + i*256];
        vals[i] = v; ss += v*v;
    }
    __shared__ float red[8];
#pragma unroll
    for (int o = 16; o; o >>= 1) ss += __shfl_xor_sync(0xffffffffu, ss, o);
    if ((tid & 31) == 0) red[tid >> 5] = ss;
    __syncthreads();
    if (tid < 32) {
        float t = (tid < 8) ? red[tid] : 0.f;
#pragma unroll
        for (int o = 4; o; o >>= 1) t += __shfl_xor_sync(0xffffffffu, t, o);
        if (tid == 0) red[0] = t;
    }
    __syncthreads();
    const float inv = rsqrtf(red[0] * (1.f/DMODEL) + 1e-6f);
    const float sk = skip ? skip[0] : 1.f;
#pragma unroll
    for (int i = 0; i < 8; i++) {
        const int d = tid + i*256;
        float o = vals[i] * inv * (1.f + (scale ? scale[d] : 0.f));
        if (resid) o += resid[base + d] * sk;
        out[base + d] = o;
    }
}

// ------------- bf16 split-3 tensor GEMM 128x128x32, 256 thr, mma.m16n8k16 -----
// x = b0 + b1 (both bf16).  acc += a0*b0 + a0*b1 + a1*b0 (drop ~2^-18 a1*b1).
__device__ __forceinline__ void split_bf(float x, u16& h, u16& l){
    __nv_bfloat16 hb = __float2bfloat16_rn(x);
    __nv_bfloat16 lb = __float2bfloat16_rn(x - __bfloat162float(hb));
    h = __bfloat16_as_ushort(hb);
    l = __bfloat16_as_ushort(lb);
}
__device__ __forceinline__ u32 pk(u16 a, u16 b){ return (u32)a | ((u32)b << 16); }

#define MMABF(d, a, b)                                                            \
    asm volatile("mma.sync.aligned.m16n8k16.row.col.f32.bf16.bf16.f32 "           \
        "{%0,%1,%2,%3}, {%4,%5,%6,%7}, {%8,%9}, {%0,%1,%2,%3};"                   \
        : "+f"(d[0]), "+f"(d[1]), "+f"(d[2]), "+f"(d[3])                          \
        : "r"(a[0]), "r"(a[1]), "r"(a[2]), "r"(a[3]), "r"(b[0]), "r"(b[1]));

// LAYB: 0 = NN (B[k][n] row-major), 1 = NT (B[n][k] row-major)
// Smem (u32 = bf16 pair along k):
//   A  : [2][128][36]  k-pairs: hi 0..15, lo 16..31, pad 4
//   BNN: [2][32][136]  rows = k-pair (hi 0..15, lo 16..31), cols = n, pad 8
//   BNT: [2][128][36]  like A (rows = n)
template<int LAYB>
__global__ __launch_bounds__(256, 2)
void gemm_bf16x3(const float* __restrict__ A, const float* __restrict__ B,
                 float* __restrict__ C, int K, int lda, int ldb, int ldc,
                 size_t wstride_z, int cstride_z)
{
    extern __shared__ u32 smemu[];
    u32* As = smemu;                      // [2][128][36]
    u32* Bs = smemu + 2*128*36;

    const int tid  = threadIdx.x;
    const int lane = tid & 31;
    const int warp = tid >> 5;
    const int wm = (warp >> 2) * 64;      // warps 2x4, warp tile 64x32
    const int wn = (warp & 3) * 32;
    const int qr = lane >> 2, qc = lane & 3;
    const int m0 = blockIdx.y * 128, n0 = blockIdx.x * 128;
    const float* Ag = A + (size_t)m0 * lda;
    const float* Bg = B + (size_t)blockIdx.z * wstride_z;

    float acc[4][4][4];
#pragma unroll
    for (int i = 0; i < 4; i++)
#pragma unroll
        for (int j = 0; j < 4; j++) {
            acc[i][j][0]=0.f; acc[i][j][1]=0.f; acc[i][j][2]=0.f; acc[i][j][3]=0.f;
        }

    auto stage = [&](int k0, int buf) {
        u32* Ab = As + buf*(128*36);
        // A: 128 rows x 32 k = 1024 float4, 4/thread
#pragma unroll
        for (int i = 0; i < 4; i++) {
            const int idx = tid + i*256;
            const int row = idx >> 3, kg = (idx & 7) * 4;
            float4 v = *(const float4*)(Ag + (size_t)row*lda + k0 + kg);
            u16 h0,l0,h1,l1,h2,l2,h3,l3;
            split_bf(v.x,h0,l0); split_bf(v.y,h1,l1);
            split_bf(v.z,h2,l2); split_bf(v.w,h3,l3);
            u32* r = Ab + row*36 + (kg >> 1);
            *(uint2*)(r)      = make_uint2(pk(h0,h1), pk(h2,h3));
            *(uint2*)(r + 16) = make_uint2(pk(l0,l1), pk(l2,l3));
        }
        if (LAYB == 0) {
            u32* Bb = Bs + buf*(32*136);
            // 16 k-pairs x 128 n: 512 slots, 2/thread, each slot 2 float4 loads
#pragma unroll
            for (int i = 0; i < 2; i++) {
                const int slot = tid + i*256;
                const int j = slot >> 5, ng = (slot & 31) * 4;
                float4 r0 = *(const float4*)(Bg + (size_t)(k0 + 2*j    )*ldb + n0 + ng);
                float4 r1 = *(const float4*)(Bg + (size_t)(k0 + 2*j + 1)*ldb + n0 + ng);
                u16 ah,al,bh,bl,ch,cl,dh,dl, eh,el,fh,fl,gh,gl,hh,hl;
                split_bf(r0.x,ah,al); split_bf(r0.y,bh,bl);
                split_bf(r0.z,ch,cl); split_bf(r0.w,dh,dl);
                split_bf(r1.x,eh,el); split_bf(r1.y,fh,fl);
                split_bf(r1.z,gh,gl); split_bf(r1.w,hh,hl);
                *(uint4*)(Bb + j*136 + ng) =
                    make_uint4(pk(ah,eh), pk(bh,fh), pk(ch,gh), pk(dh,hh));
                *(uint4*)(Bb + (j+16)*136 + ng) =
                    make_uint4(pk(al,el), pk(bl,fl), pk(cl,gl), pk(dl,hl));
            }
        } else {
            u32* Bb = Bs + buf*(128*36);
#pragma unroll
            for (int i = 0; i < 4; i++) {
                const int idx = tid + i*256;
                const int row = idx >> 3, kg = (idx & 7) * 4;
                float4 v = *(const float4*)(Bg + (size_t)(n0 + row)*ldb + k0 + kg);
                u16 h0,l0,h1,l1,h2,l2,h3,l3;
                split_bf(v.x,h0,l0); split_bf(v.y,h1,l1);
                split_bf(v.z,h2,l2); split_bf(v.w,h3,l3);
                u32* r = Bb + row*36 + (kg >> 1);
                *(uint2*)(r)      = make_uint2(pk(h0,h1), pk(h2,h3));
                *(uint2*)(r + 16) = make_uint2(pk(l0,l1), pk(l2,l3));
            }
        }
    };

    const int nIt = K / 32;
    stage(0, 0);
    __syncthreads();

    for (int it = 0; it < nIt; it++) {
        const int cur = it & 1;
        if (it + 1 < nIt) stage((it + 1) * 32, cur ^ 1);
        const u32* Ab = As + cur*(128*36);
        const u32* Bb = Bs + cur*((LAYB == 0) ? (32*136) : (128*36));
#pragma unroll
        for (int ks = 0; ks < 2; ks++) {
            const int kp = ks * 8;            // k-pair base within hi region
            u32 ah[4][4], al[4][4];
#pragma unroll
            for (int mf = 0; mf < 4; mf++) {
                const u32* p = Ab + (wm + mf*16 + qr)*36 + kp + qc;
                ah[mf][0] = p[0];       ah[mf][2] = p[4];
                ah[mf][1] = p[8*36];    ah[mf][3] = p[8*36 + 4];
                al[mf][0] = p[16];      al[mf][2] = p[20];
                al[mf][1] = p[8*36+16]; al[mf][3] = p[8*36 + 20];
            }
#pragma unroll
            for (int nf = 0; nf < 4; nf++) {
                u32 bh[2], bl[2];
                if (LAYB == 0) {
                    const u32* p = Bb + (kp + qc)*136 + wn + nf*8 + qr;
                    bh[0] = p[0];       bh[1] = p[4*136];
                    bl[0] = p[16*136];  bl[1] = p[20*136];
                } else {
                    const u32* p = Bb + (wn + nf*8 + qr)*36 + kp + qc;
                    bh[0] = p[0];  bh[1] = p[4];
                    bl[0] = p[16]; bl[1] = p[20];
                }
#pragma unroll
                for (int mf = 0; mf < 4; mf++) {
                    MMABF(acc[mf][nf], ah[mf], bh);
                    MMABF(acc[mf][nf], ah[mf], bl);
                    MMABF(acc[mf][nf], al[mf], bh);
                }
            }
        }
        __syncthreads();
    }

    const int cb = blockIdx.z * cstride_z;
#pragma unroll
    for (int mf = 0; mf < 4; mf++) {
        const int r = m0 + wm + mf*16 + qr;
#pragma unroll
        for (int nf = 0; nf < 4; nf++) {
            const int c = cb + n0 + wn + nf*8 + 2*qc;
            *(float2*)(C + (size_t)r*ldc + c)     = make_float2(acc[mf][nf][0], acc[mf][nf][1]);
            *(float2*)(C + (size_t)(r+8)*ldc + c) = make_float2(acc[mf][nf][2], acc[mf][nf][3]);
        }
    }
}

// ---------------- per-head RMSNorm + RoPE (H=256) ----------------
__global__ void qkv_post_kernel(float* __restrict__ buf, int ld,
                                const float* __restrict__ nscale,
                                const int* __restrict__ segpos,
                                int dorope)
{
    const int bt = blockIdx.x;
    const int head = blockIdx.y;
    const int h = threadIdx.x;
    float* p = buf + (size_t)bt * ld + head * HDIM;
    float v = p[h];
    __shared__ float red[8];
    __shared__ float nb[HDIM];
    float ss = v * v;
#pragma unroll
    for (int o = 16; o; o >>= 1) ss += __shfl_xor_sync(0xffffffffu, ss, o);
    if ((h & 31) == 0) red[h >> 5] = ss;
    __syncthreads();
    if (h < 32) {
        float t = (h < 8) ? red[h] : 0.f;
#pragma unroll
        for (int o = 4; o; o >>= 1) t += __shfl_xor_sync(0xffffffffu, t, o);
        if (h == 0) red[0] = t;
    }
    __syncthreads();
    float normed = v * rsqrtf(red[0] * (1.f/HDIM) + 1e-6f);
    if (nscale) normed *= (1.f + nscale[h]);
    if (dorope) {
        nb[h] = normed;
        __syncthreads();
        const int i = h & 127;
        const float ts = exp2f((float)i * (13.287712379549449f / 128.f));
        const float ang = (float)segpos[bt] / ts;
        float sn, cs;
        sincosf(ang, &sn, &cs);
        const float fi = nb[i], se = nb[i + 128];
        normed = (h < 128) ? (fi*cs - se*sn) : (se*cs + fi*sn);
    }
    p[h] = normed;
}

// ---------------- flash attention: 32 queries x 1 head per block ----------------
#define AT_TQ 32
#define AT_CS 32
#define AT_PAD 260
#define AT_SMEM ((3*AT_TQ*AT_PAD + AT_TQ*33 + 3*AT_TQ + 2*AT_TQ) * 4)

__global__ __launch_bounds__(256, 1)
void attn_kernel(const float* __restrict__ qb, const float* __restrict__ kb,
                 const float* __restrict__ vb, const int* __restrict__ segpos,
                 float* __restrict__ enc)
{
    const int b = blockIdx.z, n = blockIdx.y, tile = blockIdx.x;
    const int t0 = tile * AT_TQ;
    const int kk = n / GQA;
    extern __shared__ float sm[];
    float* Qs = sm;
    float* Ks = Qs + AT_TQ*AT_PAD;
    float* Vs = Ks + AT_CS*AT_PAD;
    float* Ps = Vs + AT_CS*AT_PAD;
    float* mrow = Ps + AT_TQ*33;
    float* lrow = mrow + AT_TQ;
    float* srow = lrow + AT_TQ;
    int*   pts  = (int*)(srow + AT_TQ);
    int*   pss  = pts + AT_TQ;

    const int tid = threadIdx.x;
    const int lane = tid & 31, warp = tid >> 5;
    const int hq = tid & 63, ig = tid >> 6;

    for (int idx = tid; idx < AT_TQ*HDIM; idx += 256) {
        const int r = idx >> 8, h = idx & 255;
        Qs[r*AT_PAD + h] = qb[((size_t)(b*TSEQ + t0 + r))*(NHEADS*HDIM) + n*HDIM + h];
    }
    if (tid < AT_TQ) {
        pts[tid] = segpos[b*TSEQ + t0 + tid];
        mrow[tid] = -1e30f; lrow[tid] = 0.f;
    }
    float acc[8][4];
#pragma unroll
    for (int i = 0; i < 8; i++)
#pragma unroll
        for (int j = 0; j < 4; j++) acc[i][j] = 0.f;

    int s_begin = t0 - (WINDOW - 1);
    if (s_begin < 0) s_begin = 0;
    s_begin &= ~(AT_CS - 1);

    for (int s0 = s_begin; s0 < t0 + AT_TQ; s0 += AT_CS) {
        __syncthreads();
        for (int idx = tid; idx < AT_CS*HDIM; idx += 256) {
            const int r = idx >> 8, h = idx & 255;
            const size_t src = ((size_t)(b*TSEQ + s0 + r))*(KVHEADS*HDIM) + kk*HDIM + h;
            Ks[r*AT_PAD + h] = kb[src];
            Vs[r*AT_PAD + h] = vb[src];
        }
        if (tid < AT_CS) pss[tid] = segpos[b*TSEQ + s0 + tid];
        __syncthreads();

        float sv[4] = {0.f, 0.f, 0.f, 0.f};
        const float4* K4 = (const float4*)(Ks + lane*AT_PAD);
#pragma unroll 8
        for (int h4 = 0; h4 < 64; h4++) {
            const float4 kvv = K4[h4];
#pragma unroll
            for (int rr = 0; rr < 4; rr++) {
                const float4 qv = *(const float4*)(Qs + (warp + rr*8)*AT_PAD + h4*4);
                sv[rr] += qv.x*kvv.x + qv.y*kvv.y + qv.z*kvv.z + qv.w*kvv.w;
            }
        }
        const int ps = pss[lane];
        const int sg = s0 + lane;
#pragma unroll
        for (int rr = 0; rr < 4; rr++) {
            const int r = warp + rr*8;
            const int tg = t0 + r;
            const int pt = pts[r];
            float s = tanhf(sv[rr] * (1.f/SOFTCAP)) * SOFTCAP;
            const bool valid = (sg <= tg) && (ps > pt - WINDOW) && (ps < pt + WINDOW);
            if (!valid) s = -1e30f;
            float mc = s;
#pragma unroll
            for (int o = 16; o; o >>= 1) mc = fmaxf(mc, __shfl_xor_sync(0xffffffffu, mc, o));
            const float mold = mrow[r];
            const float mnew = fmaxf(mold, mc);
            const float p = __expf(s - mnew);
            float pr = p;
#pragma unroll
            for (int o = 16; o; o >>= 1) pr += __shfl_xor_sync(0xffffffffu, pr, o);
            Ps[r*33 + lane] = p;
            if (lane == 0) {
                const float sc = __expf(mold - mnew);
                srow[r] = sc;
                lrow[r] = lrow[r]*sc + pr;
                mrow[r] = mnew;
            }
        }
        __syncthreads();

#pragma unroll
        for (int rr = 0; rr < 8; rr++) {
            const float sc = srow[ig*8 + rr];
            acc[rr][0]*=sc; acc[rr][1]*=sc; acc[rr][2]*=sc; acc[rr][3]*=sc;
        }
#pragma unroll 4
        for (int j = 0; j < AT_CS; j++) {
            const float4 vv = *(const float4*)(Vs + j*AT_PAD + hq*4);
#pragma unroll
            for (int rr = 0; rr < 8; rr++) {
                const float p = Ps[(ig*8+rr)*33 + j];
                acc[rr][0] += p*vv.x; acc[rr][1] += p*vv.y;
                acc[rr][2] += p*vv.z; acc[rr][3] += p*vv.w;
            }
        }
    }
    __syncthreads();
#pragma unroll
    for (int rr = 0; rr < 8; rr++) {
        const int r = ig*8 + rr;
        const float inv = 1.f / lrow[r];
        float4 o = make_float4(acc[rr][0]*inv, acc[rr][1]*inv, acc[rr][2]*inv, acc[rr][3]*inv);
        *(float4*)(enc + ((size_t)(b*TSEQ + t0 + r))*(NHEADS*HDIM) + n*HDIM + hq*4) = o;
    }
}

// ---------------- gated GELU ----------------
__global__ void act_kernel(const float* __restrict__ gates, float* __restrict__ act)
{
    const int i = blockIdx.x * blockDim.x + threadIdx.x;
    if (i >= BT*FFDIM) return;
    const int bt = i >> 13;
    const int f = i & (FFDIM - 1);
    const float x0 = gates[(size_t)bt*(2*FFDIM) + f];
    const float x1 = gates[(size_t)bt*(2*FFDIM) + FFDIM + f];
    const float g = 0.5f*x0*(1.f + tanhf(0.7978845608028654f*(x0 + 0.044715f*x0*x0*x0)));
    act[i] = g * x1;
}

// ---------------- launch ----------------
static float* symaddr(const void* sym) {
    void* p = nullptr;
    cudaGetSymbolAddress(&p, sym);
    return (float*)p;
}

#define SMEM_NN ((2*128*36 + 2*32*136) * 4)
#define SMEM_NT ((2*128*36 + 2*128*36) * 4)

extern "C" void kernel_launch(void* const* d_in, const int* in_sizes, int n_in,
                              void* d_out, int out_size)
{
    const float* x        = (const float*)d_in[0];
    const int*   segpos   = (const int*)  d_in[1];
    const float* w_q      = (const float*)d_in[7];
    const float* w_kv     = (const float*)d_in[8];
    const float* w_avec   = (const float*)d_in[9];
    const float* q_norm   = (const float*)d_in[10];
    const float* k_norm   = (const float*)d_in[11];
    const float* pre_attn = (const float*)d_in[12];
    const float* post_attn= (const float*)d_in[13];
    const float* pre_ffw  = (const float*)d_in[14];
    const float* post_ffw = (const float*)d_in[15];
    const float* w_gating = (const float*)d_in[16];
    const float* w_linear = (const float*)d_in[17];
    const float* skip     = (const float*)d_in[18];

    float* h    = symaddr(g_h);
    float* q    = symaddr(g_q);
    float* k    = symaddr(g_k);
    float* v    = symaddr(g_v);
    float* enc  = symaddr(g_enc);
    float* aproj= symaddr(g_aproj);
    float* ares = symaddr(g_ares);
    float* ffin = symaddr(g_ffin);
    float* gates= symaddr(g_gates);
    float* act  = symaddr(g_act);
    float* fout = symaddr(g_fout);

    cudaFuncSetAttribute(gemm_bf16x3<0>, cudaFuncAttributeMaxDynamicSharedMemorySize, SMEM_NN);
    cudaFuncSetAttribute(gemm_bf16x3<1>, cudaFuncAttributeMaxDynamicSharedMemorySize, SMEM_NT);
    cudaFuncSetAttribute(attn_kernel,    cudaFuncAttributeMaxDynamicSharedMemorySize, AT_SMEM);

    // 1) pre-attn RMSNorm
    rows_norm_kernel<<<BT, 256>>>(x, pre_attn, nullptr, nullptr, h);

    // 2) projections (bf16 split-3 tensor cores, per-head via grid.z)
    gemm_bf16x3<0><<<dim3(HDIM/128, BT/128, NHEADS), 256, SMEM_NN>>>(
        h, w_q, q, DMODEL, DMODEL, HDIM, NHEADS*HDIM, (size_t)DMODEL*HDIM, HDIM);
    gemm_bf16x3<0><<<dim3(HDIM/128, BT/128, KVHEADS), 256, SMEM_NN>>>(
        h, w_kv, k, DMODEL, DMODEL, HDIM, KVHEADS*HDIM, (size_t)DMODEL*HDIM, HDIM);
    gemm_bf16x3<0><<<dim3(HDIM/128, BT/128, KVHEADS), 256, SMEM_NN>>>(
        h, w_kv + (size_t)KVHEADS*DMODEL*HDIM, v, DMODEL, DMODEL, HDIM, KVHEADS*HDIM,
        (size_t)DMODEL*HDIM, HDIM);

    // 3) q/k/v norms + rope
    qkv_post_kernel<<<dim3(BT, NHEADS), 256>>>(q, NHEADS*HDIM, q_norm, segpos, 1);
    qkv_post_kernel<<<dim3(BT, KVHEADS), 256>>>(k, KVHEADS*HDIM, k_norm, segpos, 1);
    qkv_post_kernel<<<dim3(BT, KVHEADS), 256>>>(v, KVHEADS*HDIM, nullptr, segpos, 0);

    // 4) attention
    attn_kernel<<<dim3(TSEQ/AT_TQ, NHEADS, BATCH), 256, AT_SMEM>>>(q, k, v, segpos, enc);

    // 5) attn output projection
    gemm_bf16x3<0><<<dim3(DMODEL/128, BT/128, 1), 256, SMEM_NN>>>(
        enc, w_avec, aproj, NHEADS*HDIM, NHEADS*HDIM, DMODEL, DMODEL, 0, 0);

    // 6) post-attn norm + residual
    rows_norm_kernel<<<BT, 256>>>(aproj, post_attn, x, skip, ares);

    // 7) pre-ffw norm
    rows_norm_kernel<<<BT, 256>>>(ares, pre_ffw, nullptr, nullptr, ffin);

    // 8) gating GEMM (NT, both gates in one 16384-wide GEMM)
    gemm_bf16x3<1><<<dim3((2*FFDIM)/128, BT/128, 1), 256, SMEM_NT>>>(
        ffin, w_gating, gates, DMODEL, DMODEL, DMODEL, 2*FFDIM, 0, 0);

    // 9) gated gelu
    act_kernel<<<(BT*FFDIM + 255)/256, 256>>>(gates, act);

    // 10) down projection
    gemm_bf16x3<0><<<dim3(DMODEL/128, BT/128, 1), 256, SMEM_NN>>>(
        act, w_linear, fout, FFDIM, FFDIM, DMODEL, DMODEL, 0, 0);

    // 11) final: out = ares + rmsnorm(fout, post_ffw)
    rows_norm_kernel<<<BT, 256>>>(fout, post_ffw, ares, nullptr, (float*)d_out);
}

// round 9
// speedup vs baseline: 2.8922x; 1.3036x over previous
#include <cuda_runtime.h>
#include <cuda_bf16.h>
#include <stdint.h>
#include <math.h>

// ---------------- problem constants ----------------
#define BATCH 2
#define TSEQ 2048
#define BT (BATCH*TSEQ)          // 4096
#define DMODEL 2048
#define NHEADS 8
#define KVHEADS 4
#define GQA (NHEADS/KVHEADS)     // 2
#define HDIM 256
#define FFDIM 8192
#define WINDOW 1024
#define SOFTCAP 50.0f

typedef unsigned int u32;
typedef unsigned short u16;
typedef __nv_bfloat16 bf16;

// ---------------- scratch (no cudaMalloc allowed) ----------------
__device__ float g_q    [(size_t)BT*NHEADS*HDIM];          // [4096][2048]
__device__ float g_kv   [(size_t)BT*2*KVHEADS*HDIM];       // [4096][2048] k|v
__device__ float g_aproj[(size_t)BT*DMODEL];
__device__ float g_ares [(size_t)BT*DMODEL];
__device__ float g_gates[(size_t)BT*2*FFDIM];
__device__ float g_fout [(size_t)BT*DMODEL];

__device__ bf16 g_h_hi   [(size_t)BT*DMODEL];
__device__ bf16 g_h_lo   [(size_t)BT*DMODEL];
__device__ bf16 g_enc_hi [(size_t)BT*NHEADS*HDIM];
__device__ bf16 g_enc_lo [(size_t)BT*NHEADS*HDIM];
__device__ bf16 g_ffin_hi[(size_t)BT*DMODEL];
__device__ bf16 g_ffin_lo[(size_t)BT*DMODEL];
__device__ bf16 g_act_hi [(size_t)BT*FFDIM];
__device__ bf16 g_act_lo [(size_t)BT*FFDIM];

__device__ bf16 g_wq_hi [(size_t)NHEADS*HDIM*DMODEL];      // [2048][2048] (n,h) x d
__device__ bf16 g_wq_lo [(size_t)NHEADS*HDIM*DMODEL];
__device__ bf16 g_wkv_hi[(size_t)2*KVHEADS*HDIM*DMODEL];   // [2048][2048]
__device__ bf16 g_wkv_lo[(size_t)2*KVHEADS*HDIM*DMODEL];
__device__ bf16 g_wav_hi[(size_t)DMODEL*NHEADS*HDIM];      // [2048 d][2048 (n,h)]
__device__ bf16 g_wav_lo[(size_t)DMODEL*NHEADS*HDIM];
__device__ bf16 g_wg_hi [(size_t)2*FFDIM*DMODEL];          // [16384][2048]
__device__ bf16 g_wg_lo [(size_t)2*FFDIM*DMODEL];
__device__ bf16 g_wl_hi [(size_t)DMODEL*FFDIM];            // [2048 d][8192 f]
__device__ bf16 g_wl_lo [(size_t)DMODEL*FFDIM];

// ---------------- helpers ----------------
__device__ __forceinline__ void split_bf(float x, bf16& h, bf16& l){
    h = __float2bfloat16_rn(x);
    l = __float2bfloat16_rn(x - __bfloat162float(h));
}
__device__ __forceinline__ u32 pk(bf16 a, bf16 b){
    return (u32)__bfloat16_as_ushort(a) | ((u32)__bfloat16_as_ushort(b) << 16);
}

// ---------------- row-wise RMSNorm (D=2048): f32 out and/or bf16 planes ----------------
__global__ void rows_norm_kernel(const float* __restrict__ in,
                                 const float* __restrict__ scale,
                                 const float* __restrict__ resid,
                                 const float* __restrict__ skip,
                                 float* __restrict__ outf,
                                 bf16* __restrict__ ohi,
                                 bf16* __restrict__ olo)
{
    const int row = blockIdx.x;
    const int tid = threadIdx.x;
    const size_t base = (size_t)row * DMODEL;
    float vals[8];
    float ss = 0.f;
#pragma unroll
    for (int i = 0; i < 8; i++) {
        float v = in[base + tid + i*256];
        vals[i] = v; ss += v*v;
    }
    __shared__ float red[8];
#pragma unroll
    for (int o = 16; o; o >>= 1) ss += __shfl_xor_sync(0xffffffffu, ss, o);
    if ((tid & 31) == 0) red[tid >> 5] = ss;
    __syncthreads();
    if (tid < 32) {
        float t = (tid < 8) ? red[tid] : 0.f;
#pragma unroll
        for (int o = 4; o; o >>= 1) t += __shfl_xor_sync(0xffffffffu, t, o);
        if (tid == 0) red[0] = t;
    }
    __syncthreads();
    const float inv = rsqrtf(red[0] * (1.f/DMODEL) + 1e-6f);
    const float sk = skip ? skip[0] : 1.f;
#pragma unroll
    for (int i = 0; i < 8; i++) {
        const int d = tid + i*256;
        float o = vals[i] * inv * (1.f + (scale ? scale[d] : 0.f));
        if (resid) o += resid[base + d] * sk;
        if (outf) outf[base + d] = o;
        if (ohi) { bf16 h,l; split_bf(o,h,l); ohi[base+d]=h; olo[base+d]=l; }
    }
}

// ---------------- weight conversion: elementwise split ----------------
__global__ void split_kernel(const float* __restrict__ src,
                             bf16* __restrict__ hi, bf16* __restrict__ lo, int n4)
{
    const int i = blockIdx.x * blockDim.x + threadIdx.x;
    if (i >= n4) return;
    float4 v = ((const float4*)src)[i];
    bf16 h0,l0,h1,l1,h2,l2,h3,l3;
    split_bf(v.x,h0,l0); split_bf(v.y,h1,l1);
    split_bf(v.z,h2,l2); split_bf(v.w,h3,l3);
    ((uint2*)hi)[i] = make_uint2(pk(h0,h1), pk(h2,h3));
    ((uint2*)lo)[i] = make_uint2(pk(l0,l1), pk(l2,l3));
}

// ---------------- weight conversion: transpose + split ----------------
// src [R][C] f32 (+ z*src_zstride) -> planes[(dstrow0 + z*dstrow_z + c)][r], plane ld = dld
__global__ void trans_split_kernel(const float* __restrict__ src,
                                   bf16* __restrict__ hi, bf16* __restrict__ lo,
                                   int R, int C, size_t src_zstride,
                                   int dstrow0, int dstrow_z, int dld)
{
    src += (size_t)blockIdx.z * src_zstride;
    const int r0 = blockIdx.y * 32, c0 = blockIdx.x * 32;
    __shared__ float t[32][33];
    const int tx = threadIdx.x & 31, ty = threadIdx.x >> 5;   // 256 thr
#pragma unroll
    for (int i = 0; i < 4; i++) {
        const int r = r0 + ty + i*8;
        t[ty + i*8][tx] = src[(size_t)r*C + c0 + tx];
    }
    __syncthreads();
    const int drow0 = dstrow0 + blockIdx.z * dstrow_z;
#pragma unroll
    for (int i = 0; i < 4; i++) {
        const int c = c0 + ty + i*8;
        const int r = r0 + tx;
        const float v = t[tx][ty + i*8];
        bf16 h,l; split_bf(v,h,l);
        const size_t o = (size_t)(drow0 + c)*dld + r;
        hi[o] = h; lo[o] = l;
    }
}

// ------------- bf16 split-3 NT GEMM, pre-split planes, cp.async + ldmatrix -------------
// A planes [M][K], B planes [N][K], C f32 [M][ldc]. 128x128x32 tiles, 256 thr.
#define MMABF(d, a, b)                                                            \
    asm volatile("mma.sync.aligned.m16n8k16.row.col.f32.bf16.bf16.f32 "           \
        "{%0,%1,%2,%3}, {%4,%5,%6,%7}, {%8,%9}, {%0,%1,%2,%3};"                   \
        : "+f"(d[0]), "+f"(d[1]), "+f"(d[2]), "+f"(d[3])                          \
        : "r"(a[0]), "r"(a[1]), "r"(a[2]), "r"(a[3]), "r"(b[0]), "r"(b[1]));
#define LDM4(r0,r1,r2,r3,a)                                                       \
    asm volatile("ldmatrix.sync.aligned.m8n8.x4.shared.b16 {%0,%1,%2,%3}, [%4];"  \
        : "=r"(r0), "=r"(r1), "=r"(r2), "=r"(r3) : "r"(a));
#define CPA(dst, src)                                                             \
    asm volatile("cp.async.cg.shared.global [%0], [%1], 16;" :: "r"(dst), "l"(src))

// smem per buffer (u32): Ah[0..2048) Al[2048..) Bh[4096..) Bl[6144..); 2 buffers
#define GSM_BUF 8192
#define GSM_TOTAL (2*GSM_BUF*4)

__global__ __launch_bounds__(256, 2)
void gemm_planes_nt(const bf16* __restrict__ Ah, const bf16* __restrict__ Al,
                    const bf16* __restrict__ Bh, const bf16* __restrict__ Bl,
                    float* __restrict__ C, int K, int ldc)
{
    extern __shared__ u32 smemu[];
    const u32 sbase = (u32)__cvta_generic_to_shared(smemu);

    const int tid  = threadIdx.x;
    const int lane = tid & 31;
    const int warp = tid >> 5;
    const int wm = (warp >> 2) * 64;      // warps 2x4, warp tile 64x32
    const int wn = (warp & 3) * 32;
    const int qr = lane >> 2, qc = lane & 3;
    const int m0 = blockIdx.y * 128, n0 = blockIdx.x * 128;

    float acc[4][4][4];
#pragma unroll
    for (int i = 0; i < 4; i++)
#pragma unroll
        for (int j = 0; j < 4; j++) {
            acc[i][j][0]=0.f; acc[i][j][1]=0.f; acc[i][j][2]=0.f; acc[i][j][3]=0.f;
        }

    auto stage = [&](int k0, int buf) {
#pragma unroll
        for (int i = 0; i < 8; i++) {
            const int id = tid + i*256;
            const int plane = id >> 9;          // 0:Ah 1:Al 2:Bh 3:Bl
            const int wi = id & 511;
            const int row = wi >> 2, g = wi & 3;
            const bf16* sp;
            if      (plane == 0) sp = Ah + (size_t)(m0 + row)*K;
            else if (plane == 1) sp = Al + (size_t)(m0 + row)*K;
            else if (plane == 2) sp = Bh + (size_t)(n0 + row)*K;
            else                 sp = Bl + (size_t)(n0 + row)*K;
            const u32 dst = sbase + (buf*GSM_BUF + plane*2048 + row*16 +
                                     ((g ^ ((row & 7) >> 1)) << 2)) * 4;
            CPA(dst, sp + k0 + g*8);
        }
        asm volatile("cp.async.commit_group;");
    };

    const int nIt = K / 32;
    stage(0, 0);

    for (int it = 0; it < nIt; it++) {
        const int cur = it & 1;
        const bool more = (it + 1 < nIt);
        if (more) stage((it + 1) * 32, cur ^ 1);
        if (more) asm volatile("cp.async.wait_group 1;");
        else      asm volatile("cp.async.wait_group 0;");
        __syncthreads();

        const u32 abase = sbase + (cur*GSM_BUF)*4;   // byte base of buffer
        const int b = lane & 7, t = lane >> 3;
#pragma unroll
        for (int ks = 0; ks < 2; ks++) {
            // B fragments: np covers nf pairs
            u32 bh[4][2], bl[4][2];
#pragma unroll
            for (int np = 0; np < 2; np++) {
                const int row = wn + np*16 + ((t & 2) << 2) + b;
                const int g = 2*ks + (t & 1);
                const u32 off = (row*16 + ((g ^ (b >> 1)) << 2)) * 4;
                u32 r0,r1,r2,r3;
                LDM4(r0,r1,r2,r3, abase + 4096*4 + off);
                bh[2*np][0]=r0; bh[2*np][1]=r1; bh[2*np+1][0]=r2; bh[2*np+1][1]=r3;
                LDM4(r0,r1,r2,r3, abase + 6144*4 + off);
                bl[2*np][0]=r0; bl[2*np][1]=r1; bl[2*np+1][0]=r2; bl[2*np+1][1]=r3;
            }
#pragma unroll
            for (int mf = 0; mf < 4; mf++) {
                const int row = wm + mf*16 + ((t & 1) << 3) + b;
                const int g = 2*ks + (t >> 1);
                const u32 off = (row*16 + ((g ^ (b >> 1)) << 2)) * 4;
                u32 ah[4], al[4];
                LDM4(ah[0],ah[1],ah[2],ah[3], abase + off);
                LDM4(al[0],al[1],al[2],al[3], abase + 2048*4 + off);
#pragma unroll
                for (int nf = 0; nf < 4; nf++) {
                    MMABF(acc[mf][nf], ah, bh[nf]);
                    MMABF(acc[mf][nf], ah, bl[nf]);
                    MMABF(acc[mf][nf], al, bh[nf]);
                }
            }
        }
        __syncthreads();
    }

#pragma unroll
    for (int mf = 0; mf < 4; mf++) {
        const int r = m0 + wm + mf*16 + qr;
#pragma unroll
        for (int nf = 0; nf < 4; nf++) {
            const int c = n0 + wn + nf*8 + 2*qc;
            *(float2*)(C + (size_t)r*ldc + c)     = make_float2(acc[mf][nf][0], acc[mf][nf][1]);
            *(float2*)(C + (size_t)(r+8)*ldc + c) = make_float2(acc[mf][nf][2], acc[mf][nf][3]);
        }
    }
}

// ---------------- per-head RMSNorm + RoPE (H=256) ----------------
__global__ void qkv_post_kernel(float* __restrict__ buf, int ld,
                                const float* __restrict__ nscale,
                                const int* __restrict__ segpos,
                                int dorope)
{
    const int bt = blockIdx.x;
    const int head = blockIdx.y;
    const int h = threadIdx.x;
    float* p = buf + (size_t)bt * ld + head * HDIM;
    float v = p[h];
    __shared__ float red[8];
    __shared__ float nb[HDIM];
    float ss = v * v;
#pragma unroll
    for (int o = 16; o; o >>= 1) ss += __shfl_xor_sync(0xffffffffu, ss, o);
    if ((h & 31) == 0) red[h >> 5] = ss;
    __syncthreads();
    if (h < 32) {
        float t = (h < 8) ? red[h] : 0.f;
#pragma unroll
        for (int o = 4; o; o >>= 1) t += __shfl_xor_sync(0xffffffffu, t, o);
        if (h == 0) red[0] = t;
    }
    __syncthreads();
    float normed = v * rsqrtf(red[0] * (1.f/HDIM) + 1e-6f);
    if (nscale) normed *= (1.f + nscale[h]);
    if (dorope) {
        nb[h] = normed;
        __syncthreads();
        const int i = h & 127;
        const float ts = exp2f((float)i * (13.287712379549449f / 128.f));
        const float ang = (float)segpos[bt] / ts;
        float sn, cs;
        sincosf(ang, &sn, &cs);
        const float fi = nb[i], se = nb[i + 128];
        normed = (h < 128) ? (fi*cs - se*sn) : (se*cs + fi*sn);
    }
    p[h] = normed;
}

// ---------------- flash attention: 32 queries x 1 head per block ----------------
#define AT_TQ 32
#define AT_CS 32
#define AT_PAD 260
#define AT_SMEM ((3*AT_TQ*AT_PAD + AT_TQ*33 + 3*AT_TQ + 2*AT_TQ) * 4)

__global__ __launch_bounds__(256, 1)
void attn_kernel(const float* __restrict__ qb, const float* __restrict__ kvb,
                 const int* __restrict__ segpos,
                 bf16* __restrict__ ehi, bf16* __restrict__ elo)
{
    const int b = blockIdx.z, n = blockIdx.y, tile = blockIdx.x;
    const int t0 = tile * AT_TQ;
    const int kk = n / GQA;
    extern __shared__ float sm[];
    float* Qs = sm;
    float* Ks = Qs + AT_TQ*AT_PAD;
    float* Vs = Ks + AT_CS*AT_PAD;
    float* Ps = Vs + AT_CS*AT_PAD;
    float* mrow = Ps + AT_TQ*33;
    float* lrow = mrow + AT_TQ;
    float* srow = lrow + AT_TQ;
    int*   pts  = (int*)(srow + AT_TQ);
    int*   pss  = pts + AT_TQ;

    const int tid = threadIdx.x;
    const int lane = tid & 31, warp = tid >> 5;
    const int hq = tid & 63, ig = tid >> 6;

    for (int idx = tid; idx < AT_TQ*HDIM; idx += 256) {
        const int r = idx >> 8, h = idx & 255;
        Qs[r*AT_PAD + h] = qb[((size_t)(b*TSEQ + t0 + r))*(NHEADS*HDIM) + n*HDIM + h];
    }
    if (tid < AT_TQ) {
        pts[tid] = segpos[b*TSEQ + t0 + tid];
        mrow[tid] = -1e30f; lrow[tid] = 0.f;
    }
    float acc[8][4];
#pragma unroll
    for (int i = 0; i < 8; i++)
#pragma unroll
        for (int j = 0; j < 4; j++) acc[i][j] = 0.f;

    int s_begin = t0 - (WINDOW - 1);
    if (s_begin < 0) s_begin = 0;
    s_begin &= ~(AT_CS - 1);

    for (int s0 = s_begin; s0 < t0 + AT_TQ; s0 += AT_CS) {
        __syncthreads();
        for (int idx = tid; idx < AT_CS*HDIM; idx += 256) {
            const int r = idx >> 8, h = idx & 255;
            const size_t src = ((size_t)(b*TSEQ + s0 + r))*(2*KVHEADS*HDIM) + kk*HDIM + h;
            Ks[r*AT_PAD + h] = kvb[src];
            Vs[r*AT_PAD + h] = kvb[src + KVHEADS*HDIM];
        }
        if (tid < AT_CS) pss[tid] = segpos[b*TSEQ + s0 + tid];
        __syncthreads();

        float sv[4] = {0.f, 0.f, 0.f, 0.f};
        const float4* K4 = (const float4*)(Ks + lane*AT_PAD);
#pragma unroll 8
        for (int h4 = 0; h4 < 64; h4++) {
            const float4 kvv = K4[h4];
#pragma unroll
            for (int rr = 0; rr < 4; rr++) {
                const float4 qv = *(const float4*)(Qs + (warp + rr*8)*AT_PAD + h4*4);
                sv[rr] += qv.x*kvv.x + qv.y*kvv.y + qv.z*kvv.z + qv.w*kvv.w;
            }
        }
        const int ps = pss[lane];
        const int sg = s0 + lane;
#pragma unroll
        for (int rr = 0; rr < 4; rr++) {
            const int r = warp + rr*8;
            const int tg = t0 + r;
            const int pt = pts[r];
            float s = tanhf(sv[rr] * (1.f/SOFTCAP)) * SOFTCAP;
            const bool valid = (sg <= tg) && (ps > pt - WINDOW) && (ps < pt + WINDOW);
            if (!valid) s = -1e30f;
            float mc = s;
#pragma unroll
            for (int o = 16; o; o >>= 1) mc = fmaxf(mc, __shfl_xor_sync(0xffffffffu, mc, o));
            const float mold = mrow[r];
            const float mnew = fmaxf(mold, mc);
            const float p = __expf(s - mnew);
            float pr = p;
#pragma unroll
            for (int o = 16; o; o >>= 1) pr += __shfl_xor_sync(0xffffffffu, pr, o);
            Ps[r*33 + lane] = p;
            if (lane == 0) {
                const float sc = __expf(mold - mnew);
                srow[r] = sc;
                lrow[r] = lrow[r]*sc + pr;
                mrow[r] = mnew;
            }
        }
        __syncthreads();

#pragma unroll
        for (int rr = 0; rr < 8; rr++) {
            const float sc = srow[ig*8 + rr];
            acc[rr][0]*=sc; acc[rr][1]*=sc; acc[rr][2]*=sc; acc[rr][3]*=sc;
        }
#pragma unroll 4
        for (int j = 0; j < AT_CS; j++) {
            const float4 vv = *(const float4*)(Vs + j*AT_PAD + hq*4);
#pragma unroll
            for (int rr = 0; rr < 8; rr++) {
                const float p = Ps[(ig*8+rr)*33 + j];
                acc[rr][0] += p*vv.x; acc[rr][1] += p*vv.y;
                acc[rr][2] += p*vv.z; acc[rr][3] += p*vv.w;
            }
        }
    }
    __syncthreads();
#pragma unroll
    for (int rr = 0; rr < 8; rr++) {
        const int r = ig*8 + rr;
        const float inv = 1.f / lrow[r];
        float o0 = acc[rr][0]*inv, o1 = acc[rr][1]*inv,
              o2 = acc[rr][2]*inv, o3 = acc[rr][3]*inv;
        bf16 h0,l0,h1,l1,h2,l2,h3,l3;
        split_bf(o0,h0,l0); split_bf(o1,h1,l1);
        split_bf(o2,h2,l2); split_bf(o3,h3,l3);
        const size_t eb = ((size_t)(b*TSEQ + t0 + r))*(NHEADS*HDIM) + n*HDIM + hq*4;
        *(uint2*)(ehi + eb) = make_uint2(pk(h0,h1), pk(h2,h3));
        *(uint2*)(elo + eb) = make_uint2(pk(l0,l1), pk(l2,l3));
    }
}

// ---------------- gated GELU -> bf16 planes ----------------
__global__ void act_kernel(const float* __restrict__ gates,
                           bf16* __restrict__ ahi, bf16* __restrict__ alo)
{
    const int i = blockIdx.x * blockDim.x + threadIdx.x;
    if (i >= BT*FFDIM) return;
    const int bt = i >> 13;
    const int f = i & (FFDIM - 1);
    const float x0 = gates[(size_t)bt*(2*FFDIM) + f];
    const float x1 = gates[(size_t)bt*(2*FFDIM) + FFDIM + f];
    const float g = 0.5f*x0*(1.f + tanhf(0.7978845608028654f*(x0 + 0.044715f*x0*x0*x0)));
    const float a = g * x1;
    bf16 h,l; split_bf(a,h,l);
    ahi[i] = h; alo[i] = l;
}

// ---------------- launch ----------------
template<typename T>
static T* symaddr(const void* sym) {
    void* p = nullptr;
    cudaGetSymbolAddress(&p, sym);
    return (T*)p;
}

extern "C" void kernel_launch(void* const* d_in, const int* in_sizes, int n_in,
                              void* d_out, int out_size)
{
    const float* x        = (const float*)d_in[0];
    const int*   segpos   = (const int*)  d_in[1];
    const float* w_q      = (const float*)d_in[7];
    const float* w_kv     = (const float*)d_in[8];
    const float* w_avec   = (const float*)d_in[9];
    const float* q_norm   = (const float*)d_in[10];
    const float* k_norm   = (const float*)d_in[11];
    const float* pre_attn = (const float*)d_in[12];
    const float* post_attn= (const float*)d_in[13];
    const float* pre_ffw  = (const float*)d_in[14];
    const float* post_ffw = (const float*)d_in[15];
    const float* w_gating = (const float*)d_in[16];
    const float* w_linear = (const float*)d_in[17];
    const float* skip     = (const float*)d_in[18];

    float* q    = symaddr<float>(g_q);
    float* kv   = symaddr<float>(g_kv);
    float* aproj= symaddr<float>(g_aproj);
    float* ares = symaddr<float>(g_ares);
    float* gates= symaddr<float>(g_gates);
    float* fout = symaddr<float>(g_fout);
    bf16* h_hi = symaddr<bf16>(g_h_hi),    *h_lo = symaddr<bf16>(g_h_lo);
    bf16* e_hi = symaddr<bf16>(g_enc_hi),  *e_lo = symaddr<bf16>(g_enc_lo);
    bf16* f_hi = symaddr<bf16>(g_ffin_hi), *f_lo = symaddr<bf16>(g_ffin_lo);
    bf16* a_hi = symaddr<bf16>(g_act_hi),  *a_lo = symaddr<bf16>(g_act_lo);
    bf16* wq_hi = symaddr<bf16>(g_wq_hi),  *wq_lo = symaddr<bf16>(g_wq_lo);
    bf16* wkv_hi= symaddr<bf16>(g_wkv_hi), *wkv_lo= symaddr<bf16>(g_wkv_lo);
    bf16* wav_hi= symaddr<bf16>(g_wav_hi), *wav_lo= symaddr<bf16>(g_wav_lo);
    bf16* wg_hi = symaddr<bf16>(g_wg_hi),  *wg_lo = symaddr<bf16>(g_wg_lo);
    bf16* wl_hi = symaddr<bf16>(g_wl_hi),  *wl_lo = symaddr<bf16>(g_wl_lo);

    cudaFuncSetAttribute(gemm_planes_nt, cudaFuncAttributeMaxDynamicSharedMemorySize, GSM_TOTAL);
    cudaFuncSetAttribute(attn_kernel,    cudaFuncAttributeMaxDynamicSharedMemorySize, AT_SMEM);

    // 0) weight conversions (per-launch; stateless)
    trans_split_kernel<<<dim3(HDIM/32, DMODEL/32, NHEADS), 256>>>(
        w_q, wq_hi, wq_lo, DMODEL, HDIM, (size_t)DMODEL*HDIM, 0, HDIM, DMODEL);
    trans_split_kernel<<<dim3(HDIM/32, DMODEL/32, 2*KVHEADS), 256>>>(
        w_kv, wkv_hi, wkv_lo, DMODEL, HDIM, (size_t)DMODEL*HDIM, 0, HDIM, DMODEL);
    trans_split_kernel<<<dim3(DMODEL/32, (NHEADS*HDIM)/32, 1), 256>>>(
        w_avec, wav_hi, wav_lo, NHEADS*HDIM, DMODEL, 0, 0, 0, NHEADS*HDIM);
    trans_split_kernel<<<dim3(DMODEL/32, FFDIM/32, 1), 256>>>(
        w_linear, wl_hi, wl_lo, FFDIM, DMODEL, 0, 0, 0, FFDIM);
    split_kernel<<<(2*FFDIM*DMODEL/4 + 255)/256, 256>>>(
        w_gating, wg_hi, wg_lo, 2*FFDIM*DMODEL/4);

    // 1) pre-attn RMSNorm -> h planes
    rows_norm_kernel<<<BT, 256>>>(x, pre_attn, nullptr, nullptr, nullptr, h_hi, h_lo);

    // 2) Q and KV projections (single wide GEMMs)
    gemm_planes_nt<<<dim3((NHEADS*HDIM)/128, BT/128), 256, GSM_TOTAL>>>(
        h_hi, h_lo, wq_hi, wq_lo, q, DMODEL, NHEADS*HDIM);
    gemm_planes_nt<<<dim3((2*KVHEADS*HDIM)/128, BT/128), 256, GSM_TOTAL>>>(
        h_hi, h_lo, wkv_hi, wkv_lo, kv, DMODEL, 2*KVHEADS*HDIM);

    // 3) q/k/v norms + rope (kv buffer: k cols 0..1023, v cols 1024..2047)
    qkv_post_kernel<<<dim3(BT, NHEADS), 256>>>(q, NHEADS*HDIM, q_norm, segpos, 1);
    qkv_post_kernel<<<dim3(BT, KVHEADS), 256>>>(kv, 2*KVHEADS*HDIM, k_norm, segpos, 1);
    qkv_post_kernel<<<dim3(BT, KVHEADS), 256>>>(kv + KVHEADS*HDIM, 2*KVHEADS*HDIM,
                                                nullptr, segpos, 0);

    // 4) attention -> enc planes
    attn_kernel<<<dim3(TSEQ/AT_TQ, NHEADS, BATCH), 256, AT_SMEM>>>(q, kv, segpos, e_hi, e_lo);

    // 5) attn output projection
    gemm_planes_nt<<<dim3(DMODEL/128, BT/128), 256, GSM_TOTAL>>>(
        e_hi, e_lo, wav_hi, wav_lo, aproj, NHEADS*HDIM, DMODEL);

    // 6) post-attn norm + residual -> ares (f32)
    rows_norm_kernel<<<BT, 256>>>(aproj, post_attn, x, skip, ares, nullptr, nullptr);

    // 7) pre-ffw norm -> ffin planes
    rows_norm_kernel<<<BT, 256>>>(ares, pre_ffw, nullptr, nullptr, nullptr, f_hi, f_lo);

    // 8) gating GEMM (16384-wide)
    gemm_planes_nt<<<dim3((2*FFDIM)/128, BT/128), 256, GSM_TOTAL>>>(
        f_hi, f_lo, wg_hi, wg_lo, gates, DMODEL, 2*FFDIM);

    // 9) gated gelu -> act planes
    act_kernel<<<(BT*FFDIM + 255)/256, 256>>>(gates, a_hi, a_lo);

    // 10) down projection
    gemm_planes_nt<<<dim3(DMODEL/128, BT/128), 256, GSM_TOTAL>>>(
        a_hi, a_lo, wl_hi, wl_lo, fout, FFDIM, DMODEL);

    // 11) final: out = ares + rmsnorm(fout, post_ffw)
    rows_norm_kernel<<<BT, 256>>>(fout, post_ffw, ares, nullptr, (float*)d_out,
                                  nullptr, nullptr);
}

// round 10
// speedup vs baseline: 3.5709x; 1.2347x over previous
#include <cuda_runtime.h>
#include <cuda_bf16.h>
#include <cuda_fp16.h>
#include <stdint.h>
#include <math.h>

// ---------------- problem constants ----------------
#define BATCH 2
#define TSEQ 2048
#define BT (BATCH*TSEQ)          // 4096
#define DMODEL 2048
#define NHEADS 8
#define KVHEADS 4
#define GQA (NHEADS/KVHEADS)     // 2
#define HDIM 256
#define FFDIM 8192
#define WINDOW 1024
#define SOFTCAP 50.0f

typedef unsigned int u32;
typedef unsigned short u16;
typedef __nv_bfloat16 bf16;

// ---------------- scratch (no cudaMalloc allowed) ----------------
__device__ float g_q    [(size_t)BT*NHEADS*HDIM];          // [4096][2048]
__device__ float g_kv   [(size_t)BT*2*KVHEADS*HDIM];       // [4096][2048] k|v
__device__ float g_aproj[(size_t)BT*DMODEL];
__device__ float g_ares [(size_t)BT*DMODEL];
__device__ float g_gates[(size_t)BT*2*FFDIM];
__device__ float g_fout [(size_t)BT*DMODEL];

__device__ bf16 g_h_hi   [(size_t)BT*DMODEL];
__device__ bf16 g_h_lo   [(size_t)BT*DMODEL];
__device__ bf16 g_enc_hi [(size_t)BT*NHEADS*HDIM];
__device__ bf16 g_enc_lo [(size_t)BT*NHEADS*HDIM];
__device__ bf16 g_ffin_hi[(size_t)BT*DMODEL];
__device__ bf16 g_ffin_lo[(size_t)BT*DMODEL];
__device__ bf16 g_act_hi [(size_t)BT*FFDIM];
__device__ bf16 g_act_lo [(size_t)BT*FFDIM];

__device__ bf16 g_qp_hi[(size_t)BT*NHEADS*HDIM];           // q planes [BT][2048]
__device__ bf16 g_qp_lo[(size_t)BT*NHEADS*HDIM];
__device__ bf16 g_kp_hi[(size_t)BT*KVHEADS*HDIM];          // k planes [BT][1024]
__device__ bf16 g_kp_lo[(size_t)BT*KVHEADS*HDIM];
__device__ __half g_vp [(size_t)BT*KVHEADS*HDIM];          // v plane fp16 [BT][1024]

__device__ bf16 g_wq_hi [(size_t)NHEADS*HDIM*DMODEL];
__device__ bf16 g_wq_lo [(size_t)NHEADS*HDIM*DMODEL];
__device__ bf16 g_wkv_hi[(size_t)2*KVHEADS*HDIM*DMODEL];
__device__ bf16 g_wkv_lo[(size_t)2*KVHEADS*HDIM*DMODEL];
__device__ bf16 g_wav_hi[(size_t)DMODEL*NHEADS*HDIM];
__device__ bf16 g_wav_lo[(size_t)DMODEL*NHEADS*HDIM];
__device__ bf16 g_wg_hi [(size_t)2*FFDIM*DMODEL];
__device__ bf16 g_wg_lo [(size_t)2*FFDIM*DMODEL];
__device__ bf16 g_wl_hi [(size_t)DMODEL*FFDIM];
__device__ bf16 g_wl_lo [(size_t)DMODEL*FFDIM];

// ---------------- helpers ----------------
__device__ __forceinline__ void split_bf(float x, bf16& h, bf16& l){
    h = __float2bfloat16_rn(x);
    l = __float2bfloat16_rn(x - __bfloat162float(h));
}
__device__ __forceinline__ u32 pk(bf16 a, bf16 b){
    return (u32)__bfloat16_as_ushort(a) | ((u32)__bfloat16_as_ushort(b) << 16);
}
__device__ __forceinline__ u32 pkh(float a, float b){
    __half2 h = __floats2half2_rn(a, b);
    return *(u32*)&h;
}

// ---------------- row-wise RMSNorm (D=2048): f32 out and/or bf16 planes ----------------
__global__ void rows_norm_kernel(const float* __restrict__ in,
                                 const float* __restrict__ scale,
                                 const float* __restrict__ resid,
                                 const float* __restrict__ skip,
                                 float* __restrict__ outf,
                                 bf16* __restrict__ ohi,
                                 bf16* __restrict__ olo)
{
    const int row = blockIdx.x;
    const int tid = threadIdx.x;
    const size_t base = (size_t)row * DMODEL;
    float vals[8];
    float ss = 0.f;
#pragma unroll
    for (int i = 0; i < 8; i++) {
        float v = in[base + tid + i*256];
        vals[i] = v; ss += v*v;
    }
    __shared__ float red[8];
#pragma unroll
    for (int o = 16; o; o >>= 1) ss += __shfl_xor_sync(0xffffffffu, ss, o);
    if ((tid & 31) == 0) red[tid >> 5] = ss;
    __syncthreads();
    if (tid < 32) {
        float t = (tid < 8) ? red[tid] : 0.f;
#pragma unroll
        for (int o = 4; o; o >>= 1) t += __shfl_xor_sync(0xffffffffu, t, o);
        if (tid == 0) red[0] = t;
    }
    __syncthreads();
    const float inv = rsqrtf(red[0] * (1.f/DMODEL) + 1e-6f);
    const float sk = skip ? skip[0] : 1.f;
#pragma unroll
    for (int i = 0; i < 8; i++) {
        const int d = tid + i*256;
        float o = vals[i] * inv * (1.f + (scale ? scale[d] : 0.f));
        if (resid) o += resid[base + d] * sk;
        if (outf) outf[base + d] = o;
        if (ohi) { bf16 h,l; split_bf(o,h,l); ohi[base+d]=h; olo[base+d]=l; }
    }
}

// ---------------- weight conversion: elementwise split ----------------
__global__ void split_kernel(const float* __restrict__ src,
                             bf16* __restrict__ hi, bf16* __restrict__ lo, int n4)
{
    const int i = blockIdx.x * blockDim.x + threadIdx.x;
    if (i >= n4) return;
    float4 v = ((const float4*)src)[i];
    bf16 h0,l0,h1,l1,h2,l2,h3,l3;
    split_bf(v.x,h0,l0); split_bf(v.y,h1,l1);
    split_bf(v.z,h2,l2); split_bf(v.w,h3,l3);
    ((uint2*)hi)[i] = make_uint2(pk(h0,h1), pk(h2,h3));
    ((uint2*)lo)[i] = make_uint2(pk(l0,l1), pk(l2,l3));
}

// ---------------- weight conversion: transpose + split ----------------
__global__ void trans_split_kernel(const float* __restrict__ src,
                                   bf16* __restrict__ hi, bf16* __restrict__ lo,
                                   int R, int C, size_t src_zstride,
                                   int dstrow0, int dstrow_z, int dld)
{
    src += (size_t)blockIdx.z * src_zstride;
    const int r0 = blockIdx.y * 32, c0 = blockIdx.x * 32;
    __shared__ float t[32][33];
    const int tx = threadIdx.x & 31, ty = threadIdx.x >> 5;   // 256 thr
#pragma unroll
    for (int i = 0; i < 4; i++) {
        const int r = r0 + ty + i*8;
        t[ty + i*8][tx] = src[(size_t)r*C + c0 + tx];
    }
    __syncthreads();
    const int drow0 = dstrow0 + blockIdx.z * dstrow_z;
#pragma unroll
    for (int i = 0; i < 4; i++) {
        const int c = c0 + ty + i*8;
        const int r = r0 + tx;
        const float v = t[tx][ty + i*8];
        bf16 h,l; split_bf(v,h,l);
        const size_t o = (size_t)(drow0 + c)*dld + r;
        hi[o] = h; lo[o] = l;
    }
}

// ------------- bf16 split-3 NT GEMM, pre-split planes, cp.async + ldmatrix -------------
#define MMABF(d, a, b)                                                            \
    asm volatile("mma.sync.aligned.m16n8k16.row.col.f32.bf16.bf16.f32 "           \
        "{%0,%1,%2,%3}, {%4,%5,%6,%7}, {%8,%9}, {%0,%1,%2,%3};"                   \
        : "+f"(d[0]), "+f"(d[1]), "+f"(d[2]), "+f"(d[3])                          \
        : "r"(a[0]), "r"(a[1]), "r"(a[2]), "r"(a[3]), "r"(b[0]), "r"(b[1]));
#define MMAFP(d, a, b0_, b1_)                                                     \
    asm volatile("mma.sync.aligned.m16n8k16.row.col.f32.f16.f16.f32 "             \
        "{%0,%1,%2,%3}, {%4,%5,%6,%7}, {%8,%9}, {%0,%1,%2,%3};"                   \
        : "+f"(d[0]), "+f"(d[1]), "+f"(d[2]), "+f"(d[3])                          \
        : "r"(a[0]), "r"(a[1]), "r"(a[2]), "r"(a[3]), "r"(b0_), "r"(b1_));
#define LDM4(r0,r1,r2,r3,a)                                                       \
    asm volatile("ldmatrix.sync.aligned.m8n8.x4.shared.b16 {%0,%1,%2,%3}, [%4];"  \
        : "=r"(r0), "=r"(r1), "=r"(r2), "=r"(r3) : "r"(a));
#define LDM4T(r0,r1,r2,r3,a)                                                      \
    asm volatile("ldmatrix.sync.aligned.m8n8.x4.trans.shared.b16 {%0,%1,%2,%3}, [%4];" \
        : "=r"(r0), "=r"(r1), "=r"(r2), "=r"(r3) : "r"(a));
#define CPA(dst, src)                                                             \
    asm volatile("cp.async.cg.shared.global [%0], [%1], 16;" :: "r"(dst), "l"(src))

#define GSM_BUF 8192
#define GSM_TOTAL (2*GSM_BUF*4)

__global__ __launch_bounds__(256, 2)
void gemm_planes_nt(const bf16* __restrict__ Ah, const bf16* __restrict__ Al,
                    const bf16* __restrict__ Bh, const bf16* __restrict__ Bl,
                    float* __restrict__ C, int K, int ldc)
{
    extern __shared__ u32 smemu[];
    const u32 sbase = (u32)__cvta_generic_to_shared(smemu);

    const int tid  = threadIdx.x;
    const int lane = tid & 31;
    const int warp = tid >> 5;
    const int wm = (warp >> 2) * 64;
    const int wn = (warp & 3) * 32;
    const int qr = lane >> 2, qc = lane & 3;
    const int m0 = blockIdx.y * 128, n0 = blockIdx.x * 128;

    float acc[4][4][4];
#pragma unroll
    for (int i = 0; i < 4; i++)
#pragma unroll
        for (int j = 0; j < 4; j++) {
            acc[i][j][0]=0.f; acc[i][j][1]=0.f; acc[i][j][2]=0.f; acc[i][j][3]=0.f;
        }

    auto stage = [&](int k0, int buf) {
#pragma unroll
        for (int i = 0; i < 8; i++) {
            const int id = tid + i*256;
            const int plane = id >> 9;
            const int wi = id & 511;
            const int row = wi >> 2, g = wi & 3;
            const bf16* sp;
            if      (plane == 0) sp = Ah + (size_t)(m0 + row)*K;
            else if (plane == 1) sp = Al + (size_t)(m0 + row)*K;
            else if (plane == 2) sp = Bh + (size_t)(n0 + row)*K;
            else                 sp = Bl + (size_t)(n0 + row)*K;
            const u32 dst = sbase + (buf*GSM_BUF + plane*2048 + row*16 +
                                     ((g ^ ((row & 7) >> 1)) << 2)) * 4;
            CPA(dst, sp + k0 + g*8);
        }
        asm volatile("cp.async.commit_group;");
    };

    const int nIt = K / 32;
    stage(0, 0);

    for (int it = 0; it < nIt; it++) {
        const int cur = it & 1;
        const bool more = (it + 1 < nIt);
        if (more) stage((it + 1) * 32, cur ^ 1);
        if (more) asm volatile("cp.async.wait_group 1;");
        else      asm volatile("cp.async.wait_group 0;");
        __syncthreads();

        const u32 abase = sbase + (cur*GSM_BUF)*4;
        const int b = lane & 7, t = lane >> 3;
#pragma unroll
        for (int ks = 0; ks < 2; ks++) {
            u32 bh[4][2], bl[4][2];
#pragma unroll
            for (int np = 0; np < 2; np++) {
                const int row = wn + np*16 + ((t & 2) << 2) + b;
                const int g = 2*ks + (t & 1);
                const u32 off = (row*16 + ((g ^ (b >> 1)) << 2)) * 4;
                u32 r0,r1,r2,r3;
                LDM4(r0,r1,r2,r3, abase + 4096*4 + off);
                bh[2*np][0]=r0; bh[2*np][1]=r1; bh[2*np+1][0]=r2; bh[2*np+1][1]=r3;
                LDM4(r0,r1,r2,r3, abase + 6144*4 + off);
                bl[2*np][0]=r0; bl[2*np][1]=r1; bl[2*np+1][0]=r2; bl[2*np+1][1]=r3;
            }
#pragma unroll
            for (int mf = 0; mf < 4; mf++) {
                const int row = wm + mf*16 + ((t & 1) << 3) + b;
                const int g = 2*ks + (t >> 1);
                const u32 off = (row*16 + ((g ^ (b >> 1)) << 2)) * 4;
                u32 ah[4], al[4];
                LDM4(ah[0],ah[1],ah[2],ah[3], abase + off);
                LDM4(al[0],al[1],al[2],al[3], abase + 2048*4 + off);
#pragma unroll
                for (int nf = 0; nf < 4; nf++) {
                    MMABF(acc[mf][nf], ah, bh[nf]);
                    MMABF(acc[mf][nf], ah, bl[nf]);
                    MMABF(acc[mf][nf], al, bh[nf]);
                }
            }
        }
        __syncthreads();
    }

#pragma unroll
    for (int mf = 0; mf < 4; mf++) {
        const int r = m0 + wm + mf*16 + qr;
#pragma unroll
        for (int nf = 0; nf < 4; nf++) {
            const int c = n0 + wn + nf*8 + 2*qc;
            *(float2*)(C + (size_t)r*ldc + c)     = make_float2(acc[mf][nf][0], acc[mf][nf][1]);
            *(float2*)(C + (size_t)(r+8)*ldc + c) = make_float2(acc[mf][nf][2], acc[mf][nf][3]);
        }
    }
}

// ---------------- per-head RMSNorm + RoPE (H=256) -> split planes ----------------
__global__ void qkv_post_kernel(const float* __restrict__ buf, int ld,
                                const float* __restrict__ nscale,
                                const int* __restrict__ segpos,
                                int dorope,
                                bf16* __restrict__ ohi, bf16* __restrict__ olo,
                                __half* __restrict__ ovh, int pld)
{
    const int bt = blockIdx.x;
    const int head = blockIdx.y;
    const int h = threadIdx.x;
    const float* p = buf + (size_t)bt * ld + head * HDIM;
    float v = p[h];
    __shared__ float red[8];
    __shared__ float nb[HDIM];
    float ss = v * v;
#pragma unroll
    for (int o = 16; o; o >>= 1) ss += __shfl_xor_sync(0xffffffffu, ss, o);
    if ((h & 31) == 0) red[h >> 5] = ss;
    __syncthreads();
    if (h < 32) {
        float t = (h < 8) ? red[h] : 0.f;
#pragma unroll
        for (int o = 4; o; o >>= 1) t += __shfl_xor_sync(0xffffffffu, t, o);
        if (h == 0) red[0] = t;
    }
    __syncthreads();
    float normed = v * rsqrtf(red[0] * (1.f/HDIM) + 1e-6f);
    if (nscale) normed *= (1.f + nscale[h]);
    if (dorope) {
        nb[h] = normed;
        __syncthreads();
        const int i = h & 127;
        const float ts = exp2f((float)i * (13.287712379549449f / 128.f));
        const float ang = (float)segpos[bt] / ts;
        float sn, cs;
        sincosf(ang, &sn, &cs);
        const float fi = nb[i], se = nb[i + 128];
        normed = (h < 128) ? (fi*cs - se*sn) : (se*cs + fi*sn);
    }
    const size_t o = (size_t)bt*pld + head*HDIM + h;
    if (ohi) { bf16 hh,ll; split_bf(normed,hh,ll); ohi[o]=hh; olo[o]=ll; }
    if (ovh) ovh[o] = __float2half(normed);
}

// ---------------- tensor-core flash attention ----------------
// block: 128 queries x 1 head; 8 warps x m16 rows; 32-key chunks, double buffered.
// smem bytes: Qh 0..64K, Ql 64K..128K, KV buf0 @131072 (Kh 16K, Kl 16K, V 16K),
//             KV buf1 @180224, pts @229376 (128 int), pss @229888 (2x32 int)
#define ATT_QH   0
#define ATT_QL   65536
#define ATT_KV0  131072
#define ATT_KVSZ 49152
#define ATT_PTS  229376
#define ATT_PSS  229888
#define ATT_SMEM 230144

__global__ __launch_bounds__(256, 1)
void attn_tc_kernel(const bf16* __restrict__ qph, const bf16* __restrict__ qpl,
                    const bf16* __restrict__ kph, const bf16* __restrict__ kpl,
                    const __half* __restrict__ vp, const int* __restrict__ segpos,
                    bf16* __restrict__ ehi, bf16* __restrict__ elo)
{
    extern __shared__ char smb[];
    const u32 sb = (u32)__cvta_generic_to_shared(smb);
    int* ptsm = (int*)(smb + ATT_PTS);
    int* pssm = (int*)(smb + ATT_PSS);

    const int b = blockIdx.z, n = blockIdx.y, tile = blockIdx.x;
    const int t0 = tile * 128;
    const int kk = n / GQA;
    const int tid = threadIdx.x, lane = tid & 31, warp = tid >> 5;
    const int qr = lane >> 2, qc = lane & 3;
    const int tq0 = t0 + warp*16;
    const int rl = lane & 7, tl = lane >> 3;

    // ---- stage Q planes (group 0) ----
    {
        const size_t qbase = ((size_t)(b*TSEQ + t0))*(NHEADS*HDIM) + n*HDIM;
#pragma unroll
        for (int i = 0; i < 16; i++) {
            const int id = tid + i*256;          // row(128) x chunk(32)
            const int row = id >> 5, g = id & 31;
            const u32 dst = sb + row*512 + ((g ^ (row & 7)) << 4);
            const size_t off = qbase + (size_t)row*(NHEADS*HDIM) + g*8;
            CPA(dst, qph + off);
            CPA(dst + ATT_QL, qpl + off);
        }
        if (tid < 128) ptsm[tid] = segpos[b*TSEQ + t0 + tid];
    }
    asm volatile("cp.async.commit_group;");

    int s_begin = t0 - (WINDOW - 1); if (s_begin < 0) s_begin = 0;
    s_begin &= ~31;
    const int nch = (t0 + 128 - s_begin) >> 5;

    auto stageKV = [&](int s0, int buf) {
        const size_t kb = ((size_t)(b*TSEQ + s0))*(KVHEADS*HDIM) + kk*HDIM;
#pragma unroll
        for (int i = 0; i < 4; i++) {
            const int id = tid + i*256;          // row(32) x chunk(32)
            const int row = id >> 5, g = id & 31;
            const u32 dst = sb + ATT_KV0 + buf*ATT_KVSZ + row*512 + ((g ^ (row & 7)) << 4);
            const size_t off = kb + (size_t)row*(KVHEADS*HDIM) + g*8;
            CPA(dst,         kph + off);
            CPA(dst + 16384, kpl + off);
            CPA(dst + 32768, vp  + off);
        }
        if (tid < 32) pssm[buf*32 + tid] = segpos[b*TSEQ + s0 + tid];
        asm volatile("cp.async.commit_group;");
    };

    stageKV(s_begin, 0);     // group 1

    float acc[32][4];
#pragma unroll
    for (int j = 0; j < 32; j++) { acc[j][0]=0.f; acc[j][1]=0.f; acc[j][2]=0.f; acc[j][3]=0.f; }
    float mprev0 = -1e30f, mprev1 = -1e30f, l0 = 0.f, l1 = 0.f;

    for (int c = 0; c < nch; c++) {
        const int s0 = s_begin + c*32;
        const int cur = c & 1;
        const bool more = (c + 1 < nch);
        if (more) stageKV(s0 + 32, cur ^ 1);
        if (more) asm volatile("cp.async.wait_group 1;");
        else      asm volatile("cp.async.wait_group 0;");
        __syncthreads();

        const bool active = !(s0 > tq0 + 15 || s0 + 31 < tq0 - (WINDOW - 1));
        if (active) {
            const u32 kvb = sb + ATT_KV0 + cur*ATT_KVSZ;
            // ---- S = Q K^T (bf16 split-3) ----
            float S[4][4];
#pragma unroll
            for (int j = 0; j < 4; j++) { S[j][0]=0.f; S[j][1]=0.f; S[j][2]=0.f; S[j][3]=0.f; }
#pragma unroll
            for (int t = 0; t < 16; t++) {
                u32 aqh[4], aql[4];
                {
                    const int row = warp*16 + rl + ((tl & 1) << 3);
                    const int g = 2*t + (tl >> 1);
                    const u32 addr = sb + row*512 + ((g ^ (row & 7)) << 4);
                    LDM4(aqh[0],aqh[1],aqh[2],aqh[3], addr);
                    LDM4(aql[0],aql[1],aql[2],aql[3], addr + ATT_QL);
                }
                u32 bh[4][2], bl[4][2];
#pragma unroll
                for (int p2 = 0; p2 < 2; p2++) {
                    const int row = p2*16 + ((tl >> 1) << 3) + rl;
                    const int g = 2*t + (tl & 1);
                    const u32 addr = kvb + row*512 + ((g ^ (row & 7)) << 4);
                    u32 r0,r1,r2,r3;
                    LDM4(r0,r1,r2,r3, addr);
                    bh[2*p2][0]=r0; bh[2*p2][1]=r1; bh[2*p2+1][0]=r2; bh[2*p2+1][1]=r3;
                    LDM4(r0,r1,r2,r3, addr + 16384);
                    bl[2*p2][0]=r0; bl[2*p2][1]=r1; bl[2*p2+1][0]=r2; bl[2*p2+1][1]=r3;
                }
#pragma unroll
                for (int j = 0; j < 4; j++) {
                    MMABF(S[j], aqh, bh[j]);
                    MMABF(S[j], aqh, bl[j]);
                    MMABF(S[j], aql, bh[j]);
                }
            }
            // ---- softcap + mask ----
            const int pt0 = ptsm[warp*16 + qr], pt1 = ptsm[warp*16 + qr + 8];
            const int tg0 = tq0 + qr, tg1 = tq0 + qr + 8;
#pragma unroll
            for (int j = 0; j < 4; j++) {
#pragma unroll
                for (int e = 0; e < 2; e++) {
                    const int scol = s0 + j*8 + 2*qc + e;
                    const int ps = pssm[cur*32 + j*8 + 2*qc + e];
                    float v0 = tanhf(S[j][e] * (1.f/SOFTCAP)) * SOFTCAP;
                    S[j][e] = ((scol <= tg0) && (ps > pt0 - WINDOW) && (ps < pt0 + WINDOW))
                              ? v0 : -1e30f;
                    float v1 = tanhf(S[j][2+e] * (1.f/SOFTCAP)) * SOFTCAP;
                    S[j][2+e] = ((scol <= tg1) && (ps > pt1 - WINDOW) && (ps < pt1 + WINDOW))
                              ? v1 : -1e30f;
                }
            }
            // ---- online softmax ----
            float m0 = -1e30f, m1 = -1e30f;
#pragma unroll
            for (int j = 0; j < 4; j++) {
                m0 = fmaxf(m0, fmaxf(S[j][0], S[j][1]));
                m1 = fmaxf(m1, fmaxf(S[j][2], S[j][3]));
            }
            m0 = fmaxf(m0, __shfl_xor_sync(0xffffffffu, m0, 1));
            m0 = fmaxf(m0, __shfl_xor_sync(0xffffffffu, m0, 2));
            m1 = fmaxf(m1, __shfl_xor_sync(0xffffffffu, m1, 1));
            m1 = fmaxf(m1, __shfl_xor_sync(0xffffffffu, m1, 2));
            const float mn0 = fmaxf(mprev0, m0), mn1 = fmaxf(mprev1, m1);
            const float sc0 = __expf(mprev0 - mn0), sc1 = __expf(mprev1 - mn1);
            mprev0 = mn0; mprev1 = mn1;
            float ps0 = 0.f, ps1 = 0.f;
#pragma unroll
            for (int j = 0; j < 4; j++) {
                S[j][0] = __expf(S[j][0] - mn0); S[j][1] = __expf(S[j][1] - mn0);
                S[j][2] = __expf(S[j][2] - mn1); S[j][3] = __expf(S[j][3] - mn1);
                ps0 += S[j][0] + S[j][1];
                ps1 += S[j][2] + S[j][3];
            }
            ps0 += __shfl_xor_sync(0xffffffffu, ps0, 1);
            ps0 += __shfl_xor_sync(0xffffffffu, ps0, 2);
            ps1 += __shfl_xor_sync(0xffffffffu, ps1, 1);
            ps1 += __shfl_xor_sync(0xffffffffu, ps1, 2);
            l0 = l0*sc0 + ps0; l1 = l1*sc1 + ps1;
#pragma unroll
            for (int j = 0; j < 32; j++) {
                acc[j][0] *= sc0; acc[j][1] *= sc0;
                acc[j][2] *= sc1; acc[j][3] *= sc1;
            }
            // ---- P fp16 fragments ----
            u32 P[2][4];
#pragma unroll
            for (int ks = 0; ks < 2; ks++) {
                P[ks][0] = pkh(S[2*ks][0],   S[2*ks][1]);
                P[ks][1] = pkh(S[2*ks][2],   S[2*ks][3]);
                P[ks][2] = pkh(S[2*ks+1][0], S[2*ks+1][1]);
                P[ks][3] = pkh(S[2*ks+1][2], S[2*ks+1][3]);
            }
            // ---- O += P V (fp16) ----
#pragma unroll
            for (int ks = 0; ks < 2; ks++) {
#pragma unroll
                for (int jj = 0; jj < 16; jj++) {
                    const int row = ks*16 + ((tl & 1) << 3) + rl;
                    const int g = 2*jj + (tl >> 1);
                    const u32 addr = kvb + 32768 + row*512 + ((g ^ (row & 7)) << 4);
                    u32 r0,r1,r2,r3;
                    LDM4T(r0,r1,r2,r3, addr);
                    MMAFP(acc[2*jj],   P[ks], r0, r1);
                    MMAFP(acc[2*jj+1], P[ks], r2, r3);
                }
            }
        }
        __syncthreads();
    }

    // ---- epilogue: normalize + write enc planes ----
    const float inv0 = 1.f / l0, inv1 = 1.f / l1;
    const size_t r0b = ((size_t)(b*TSEQ + tq0 + qr))*(NHEADS*HDIM);
    const size_t r1b = ((size_t)(b*TSEQ + tq0 + qr + 8))*(NHEADS*HDIM);
#pragma unroll
    for (int j = 0; j < 32; j++) {
        const int col = n*HDIM + j*8 + 2*qc;
        float o0 = acc[j][0]*inv0, o1 = acc[j][1]*inv0;
        float o2 = acc[j][2]*inv1, o3 = acc[j][3]*inv1;
        bf16 h0,l0b,h1,l1b,h2,l2b,h3,l3b;
        split_bf(o0,h0,l0b); split_bf(o1,h1,l1b);
        split_bf(o2,h2,l2b); split_bf(o3,h3,l3b);
        *(u32*)(ehi + r0b + col) = pk(h0,h1);
        *(u32*)(elo + r0b + col) = pk(l0b,l1b);
        *(u32*)(ehi + r1b + col) = pk(h2,h3);
        *(u32*)(elo + r1b + col) = pk(l2b,l3b);
    }
}

// ---------------- gated GELU -> bf16 planes ----------------
__global__ void act_kernel(const float* __restrict__ gates,
                           bf16* __restrict__ ahi, bf16* __restrict__ alo)
{
    const int i = blockIdx.x * blockDim.x + threadIdx.x;
    if (i >= BT*FFDIM) return;
    const int bt = i >> 13;
    const int f = i & (FFDIM - 1);
    const float x0 = gates[(size_t)bt*(2*FFDIM) + f];
    const float x1 = gates[(size_t)bt*(2*FFDIM) + FFDIM + f];
    const float g = 0.5f*x0*(1.f + tanhf(0.7978845608028654f*(x0 + 0.044715f*x0*x0*x0)));
    const float a = g * x1;
    bf16 h,l; split_bf(a,h,l);
    ahi[i] = h; alo[i] = l;
}

// ---------------- launch ----------------
template<typename T>
static T* symaddr(const void* sym) {
    void* p = nullptr;
    cudaGetSymbolAddress(&p, sym);
    return (T*)p;
}

extern "C" void kernel_launch(void* const* d_in, const int* in_sizes, int n_in,
                              void* d_out, int out_size)
{
    const float* x        = (const float*)d_in[0];
    const int*   segpos   = (const int*)  d_in[1];
    const float* w_q      = (const float*)d_in[7];
    const float* w_kv     = (const float*)d_in[8];
    const float* w_avec   = (const float*)d_in[9];
    const float* q_norm   = (const float*)d_in[10];
    const float* k_norm   = (const float*)d_in[11];
    const float* pre_attn = (const float*)d_in[12];
    const float* post_attn= (const float*)d_in[13];
    const float* pre_ffw  = (const float*)d_in[14];
    const float* post_ffw = (const float*)d_in[15];
    const float* w_gating = (const float*)d_in[16];
    const float* w_linear = (const float*)d_in[17];
    const float* skip     = (const float*)d_in[18];

    float* q    = symaddr<float>(g_q);
    float* kv   = symaddr<float>(g_kv);
    float* aproj= symaddr<float>(g_aproj);
    float* ares = symaddr<float>(g_ares);
    float* gates= symaddr<float>(g_gates);
    float* fout = symaddr<float>(g_fout);
    bf16* h_hi = symaddr<bf16>(g_h_hi),    *h_lo = symaddr<bf16>(g_h_lo);
    bf16* e_hi = symaddr<bf16>(g_enc_hi),  *e_lo = symaddr<bf16>(g_enc_lo);
    bf16* f_hi = symaddr<bf16>(g_ffin_hi), *f_lo = symaddr<bf16>(g_ffin_lo);
    bf16* a_hi = symaddr<bf16>(g_act_hi),  *a_lo = symaddr<bf16>(g_act_lo);
    bf16* qp_hi = symaddr<bf16>(g_qp_hi),  *qp_lo = symaddr<bf16>(g_qp_lo);
    bf16* kp_hi = symaddr<bf16>(g_kp_hi),  *kp_lo = symaddr<bf16>(g_kp_lo);
    __half* vp  = symaddr<__half>(g_vp);
    bf16* wq_hi = symaddr<bf16>(g_wq_hi),  *wq_lo = symaddr<bf16>(g_wq_lo);
    bf16* wkv_hi= symaddr<bf16>(g_wkv_hi), *wkv_lo= symaddr<bf16>(g_wkv_lo);
    bf16* wav_hi= symaddr<bf16>(g_wav_hi), *wav_lo= symaddr<bf16>(g_wav_lo);
    bf16* wg_hi = symaddr<bf16>(g_wg_hi),  *wg_lo = symaddr<bf16>(g_wg_lo);
    bf16* wl_hi = symaddr<bf16>(g_wl_hi),  *wl_lo = symaddr<bf16>(g_wl_lo);

    cudaFuncSetAttribute(gemm_planes_nt, cudaFuncAttributeMaxDynamicSharedMemorySize, GSM_TOTAL);
    cudaFuncSetAttribute(attn_tc_kernel, cudaFuncAttributeMaxDynamicSharedMemorySize, ATT_SMEM);

    // 0) weight conversions
    trans_split_kernel<<<dim3(HDIM/32, DMODEL/32, NHEADS), 256>>>(
        w_q, wq_hi, wq_lo, DMODEL, HDIM, (size_t)DMODEL*HDIM, 0, HDIM, DMODEL);
    trans_split_kernel<<<dim3(HDIM/32, DMODEL/32, 2*KVHEADS), 256>>>(
        w_kv, wkv_hi, wkv_lo, DMODEL, HDIM, (size_t)DMODEL*HDIM, 0, HDIM, DMODEL);
    trans_split_kernel<<<dim3(DMODEL/32, (NHEADS*HDIM)/32, 1), 256>>>(
        w_avec, wav_hi, wav_lo, NHEADS*HDIM, DMODEL, 0, 0, 0, NHEADS*HDIM);
    trans_split_kernel<<<dim3(DMODEL/32, FFDIM/32, 1), 256>>>(
        w_linear, wl_hi, wl_lo, FFDIM, DMODEL, 0, 0, 0, FFDIM);
    split_kernel<<<(2*FFDIM*DMODEL/4 + 255)/256, 256>>>(
        w_gating, wg_hi, wg_lo, 2*FFDIM*DMODEL/4);

    // 1) pre-attn RMSNorm -> h planes
    rows_norm_kernel<<<BT, 256>>>(x, pre_attn, nullptr, nullptr, nullptr, h_hi, h_lo);

    // 2) projections
    gemm_planes_nt<<<dim3((NHEADS*HDIM)/128, BT/128), 256, GSM_TOTAL>>>(
        h_hi, h_lo, wq_hi, wq_lo, q, DMODEL, NHEADS*HDIM);
    gemm_planes_nt<<<dim3((2*KVHEADS*HDIM)/128, BT/128), 256, GSM_TOTAL>>>(
        h_hi, h_lo, wkv_hi, wkv_lo, kv, DMODEL, 2*KVHEADS*HDIM);

    // 3) q/k/v norms + rope -> attention planes
    qkv_post_kernel<<<dim3(BT, NHEADS), 256>>>(q, NHEADS*HDIM, q_norm, segpos, 1,
                                               qp_hi, qp_lo, nullptr, NHEADS*HDIM);
    qkv_post_kernel<<<dim3(BT, KVHEADS), 256>>>(kv, 2*KVHEADS*HDIM, k_norm, segpos, 1,
                                                kp_hi, kp_lo, nullptr, KVHEADS*HDIM);
    qkv_post_kernel<<<dim3(BT, KVHEADS), 256>>>(kv + KVHEADS*HDIM, 2*KVHEADS*HDIM,
                                                nullptr, segpos, 0,
                                                nullptr, nullptr, vp, KVHEADS*HDIM);

    // 4) tensor-core attention -> enc planes
    attn_tc_kernel<<<dim3(TSEQ/128, NHEADS, BATCH), 256, ATT_SMEM>>>(
        qp_hi, qp_lo, kp_hi, kp_lo, vp, segpos, e_hi, e_lo);

    // 5) attn output projection
    gemm_planes_nt<<<dim3(DMODEL/128, BT/128), 256, GSM_TOTAL>>>(
        e_hi, e_lo, wav_hi, wav_lo, aproj, NHEADS*HDIM, DMODEL);

    // 6) post-attn norm + residual
    rows_norm_kernel<<<BT, 256>>>(aproj, post_attn, x, skip, ares, nullptr, nullptr);

    // 7) pre-ffw norm -> ffin planes
    rows_norm_kernel<<<BT, 256>>>(ares, pre_ffw, nullptr, nullptr, nullptr, f_hi, f_lo);

    // 8) gating GEMM
    gemm_planes_nt<<<dim3((2*FFDIM)/128, BT/128), 256, GSM_TOTAL>>>(
        f_hi, f_lo, wg_hi, wg_lo, gates, DMODEL, 2*FFDIM);

    // 9) gated gelu -> act planes
    act_kernel<<<(BT*FFDIM + 255)/256, 256>>>(gates, a_hi, a_lo);

    // 10) down projection
    gemm_planes_nt<<<dim3(DMODEL/128, BT/128), 256, GSM_TOTAL>>>(
        a_hi, a_lo, wl_hi, wl_lo, fout, FFDIM, DMODEL);

    // 11) final: out = ares + rmsnorm(fout, post_ffw)
    rows_norm_kernel<<<BT, 256>>>(fout, post_ffw, ares, nullptr, (float*)d_out,
                                  nullptr, nullptr);
}